// round 1
// baseline (speedup 1.0000x reference)
#include <cuda_runtime.h>

// EdgeModel fused kernel (fp32 CUDA-core baseline, round 0)
// y = relu( relu(BN( [x[row]|x[col]|tanh(ea@W1+b1)] @ W2 + b2 )) @ W3 + b3 )
//
// Tile: 64 edges per block, 256 threads, thread tile 8 edges x 4 features.

#define TILE_E 64

__global__ __launch_bounds__(256) void edge_model_kernel(
    const float* __restrict__ x,
    const int* __restrict__ ei_words,   // edge_index as 32-bit words (dtype probed)
    const float* __restrict__ edge_attr,
    const float* __restrict__ W1, const float* __restrict__ b1,
    const float* __restrict__ W2, const float* __restrict__ b2,
    const float* __restrict__ bn_gamma, const float* __restrict__ bn_beta,
    const float* __restrict__ bn_mean, const float* __restrict__ bn_var,
    const float* __restrict__ W3, const float* __restrict__ b3,
    float* __restrict__ out, int E)
{
    __shared__ float sAT[128][65];   // staged A^T: [k][edge], scalar broadcast reads
    __shared__ float sEA[64][36];    // edge_attr tile
    __shared__ int   sRow[64], sCol[64];
    __shared__ float sScale[128], sShift[128];

    const int t  = threadIdx.x;
    const int fg = t & 31;    // feature group: features fg*4 .. fg*4+3
    const int eg = t >> 5;    // edge group: edges eg*8 .. eg*8+7
    const int ebase = blockIdx.x * TILE_E;

    // --- dtype probe: int64 edge_index has zero hi-words at odd positions ---
    const bool is64 = ((ei_words[1] | ei_words[3] | ei_words[5] | ei_words[7]) == 0);

    // --- load indices ---
    if (t < 64) {
        int e = ebase + t; if (e > E - 1) e = E - 1;
        if (is64) {
            sRow[t] = (int)((const long long*)ei_words)[e];
            sCol[t] = (int)((const long long*)ei_words)[(long long)E + e];
        } else {
            sRow[t] = ei_words[e];
            sCol[t] = ei_words[E + e];
        }
    }
    // --- folded BN scale/shift (includes b2) ---
    if (t >= 64 && t < 192) {
        int j = t - 64;
        float sc = bn_gamma[j] * rsqrtf(bn_var[j] + 1e-5f);
        sScale[j] = sc;
        sShift[j] = (b2[j] - bn_mean[j]) * sc + bn_beta[j];
    }
    // --- load edge_attr tile [64][32] ---
    {
        const float4* ea4 = (const float4*)edge_attr;
        #pragma unroll
        for (int i = 0; i < 2; i++) {
            int lin = t + i * 256;            // 0..511 float4s
            int e = lin >> 3, q = lin & 7;
            int ge = ebase + e; if (ge > E - 1) ge = E - 1;
            float4 v = ea4[(long long)ge * 8 + q];
            sEA[e][4*q+0] = v.x; sEA[e][4*q+1] = v.y;
            sEA[e][4*q+2] = v.z; sEA[e][4*q+3] = v.w;
        }
    }
    __syncthreads();

    float acc[8][4];
    #pragma unroll
    for (int i = 0; i < 8; i++) { acc[i][0]=0.f; acc[i][1]=0.f; acc[i][2]=0.f; acc[i][3]=0.f; }

    const float4* x4 = (const float4*)x;

    // ---- W2 GEMM in three K=128 chunks: x[row], x[col], e=tanh(ea@W1+b1) ----
    for (int ch = 0; ch < 3; ch++) {
        if (ch < 2) {
            const int* idx = (ch == 0) ? sRow : sCol;
            #pragma unroll
            for (int i = 0; i < 8; i++) {
                int lin = t + i * 256;        // 0..2047 float4s
                int e  = lin & 63;
                int kq = lin >> 6;            // 0..31
                float4 v = x4[(long long)idx[e] * 32 + kq];
                sAT[4*kq+0][e] = v.x; sAT[4*kq+1][e] = v.y;
                sAT[4*kq+2][e] = v.z; sAT[4*kq+3][e] = v.w;
            }
        } else {
            // compute e-tile: thread owns feature j, rows r0, r0+2, ...
            int j  = t & 127;
            int r0 = t >> 7;
            float w1r[32];
            #pragma unroll
            for (int k = 0; k < 32; k++) w1r[k] = W1[k * 128 + j];
            float bj = b1[j];
            #pragma unroll 1
            for (int r = r0; r < 64; r += 2) {
                float a = bj;
                #pragma unroll
                for (int k = 0; k < 32; k++) a += sEA[r][k] * w1r[k];
                sAT[j][r] = tanhf(a);
            }
        }
        __syncthreads();

        const float4* Wc = (const float4*)(W2 + ch * 128 * 128);
        #pragma unroll 4
        for (int k = 0; k < 128; k++) {
            float4 w = Wc[k * 32 + fg];
            #pragma unroll
            for (int i = 0; i < 8; i++) {
                float a = sAT[k][eg * 8 + i];   // warp-broadcast
                acc[i][0] += a * w.x; acc[i][1] += a * w.y;
                acc[i][2] += a * w.z; acc[i][3] += a * w.w;
            }
        }
        __syncthreads();
    }

    // ---- BN + ReLU -> sAT (transposed for second GEMM) ----
    {
        float sc[4], sh[4];
        #pragma unroll
        for (int c = 0; c < 4; c++) { sc[c] = sScale[fg*4+c]; sh[c] = sShift[fg*4+c]; }
        #pragma unroll
        for (int i = 0; i < 8; i++) {
            #pragma unroll
            for (int c = 0; c < 4; c++) {
                float h = acc[i][c] * sc[c] + sh[c];
                sAT[fg*4+c][eg*8+i] = fmaxf(h, 0.f);
            }
        }
    }
    __syncthreads();

    // ---- W3 GEMM ----
    float acc2[8][4];
    #pragma unroll
    for (int i = 0; i < 8; i++) { acc2[i][0]=0.f; acc2[i][1]=0.f; acc2[i][2]=0.f; acc2[i][3]=0.f; }

    const float4* W3v = (const float4*)W3;
    #pragma unroll 4
    for (int k = 0; k < 128; k++) {
        float4 w = W3v[k * 32 + fg];
        #pragma unroll
        for (int i = 0; i < 8; i++) {
            float a = sAT[k][eg * 8 + i];
            acc2[i][0] += a * w.x; acc2[i][1] += a * w.y;
            acc2[i][2] += a * w.z; acc2[i][3] += a * w.w;
        }
    }

    // ---- bias + ReLU + streaming store ----
    float4 bb = ((const float4*)b3)[fg];
    #pragma unroll
    for (int i = 0; i < 8; i++) {
        int e = ebase + eg * 8 + i;
        if (e < E) {
            float4 v;
            v.x = fmaxf(acc2[i][0] + bb.x, 0.f);
            v.y = fmaxf(acc2[i][1] + bb.y, 0.f);
            v.z = fmaxf(acc2[i][2] + bb.z, 0.f);
            v.w = fmaxf(acc2[i][3] + bb.w, 0.f);
            __stcs((float4*)(out + (long long)e * 128 + fg * 4), v);
        }
    }
}

extern "C" void kernel_launch(void* const* d_in, const int* in_sizes, int n_in,
                              void* d_out, int out_size) {
    const float* x         = (const float*)d_in[0];
    const int*   ei        = (const int*)  d_in[1];   // dtype probed in-kernel
    const float* edge_attr = (const float*)d_in[2];
    const float* W1        = (const float*)d_in[3];
    const float* b1        = (const float*)d_in[4];
    const float* W2        = (const float*)d_in[5];
    const float* b2        = (const float*)d_in[6];
    const float* bn_gamma  = (const float*)d_in[7];
    const float* bn_beta   = (const float*)d_in[8];
    const float* bn_mean   = (const float*)d_in[9];
    const float* bn_var    = (const float*)d_in[10];
    const float* W3        = (const float*)d_in[11];
    const float* b3        = (const float*)d_in[12];
    float* out = (float*)d_out;

    int E = in_sizes[2] / 32;                 // edge_attr is [E, 32]
    int blocks = (E + TILE_E - 1) / TILE_E;
    edge_model_kernel<<<blocks, 256>>>(x, ei, edge_attr, W1, b1, W2, b2,
                                       bn_gamma, bn_beta, bn_mean, bn_var,
                                       W3, b3, out, E);
}

// round 2
// speedup vs baseline: 1.5689x; 1.5689x over previous
#include <cuda_runtime.h>

// EdgeModel fused kernel (fp32 CUDA-core baseline, round 0)
// y = relu( relu(BN( [x[row]|x[col]|tanh(ea@W1+b1)] @ W2 + b2 )) @ W3 + b3 )
//
// Tile: 64 edges per block, 256 threads, thread tile 8 edges x 4 features.

#define TILE_E 64

__global__ __launch_bounds__(256) void edge_model_kernel(
    const float* __restrict__ x,
    const int* __restrict__ ei_words,   // edge_index as 32-bit words (dtype probed)
    const float* __restrict__ edge_attr,
    const float* __restrict__ W1, const float* __restrict__ b1,
    const float* __restrict__ W2, const float* __restrict__ b2,
    const float* __restrict__ bn_gamma, const float* __restrict__ bn_beta,
    const float* __restrict__ bn_mean, const float* __restrict__ bn_var,
    const float* __restrict__ W3, const float* __restrict__ b3,
    float* __restrict__ out, int E)
{
    __shared__ float sAT[128][65];   // staged A^T: [k][edge], scalar broadcast reads
    __shared__ float sEA[64][36];    // edge_attr tile
    __shared__ int   sRow[64], sCol[64];
    __shared__ float sScale[128], sShift[128];

    const int t  = threadIdx.x;
    const int fg = t & 31;    // feature group: features fg*4 .. fg*4+3
    const int eg = t >> 5;    // edge group: edges eg*8 .. eg*8+7
    const int ebase = blockIdx.x * TILE_E;

    // --- dtype probe: int64 edge_index has zero hi-words at odd positions ---
    const bool is64 = ((ei_words[1] | ei_words[3] | ei_words[5] | ei_words[7]) == 0);

    // --- load indices ---
    if (t < 64) {
        int e = ebase + t; if (e > E - 1) e = E - 1;
        if (is64) {
            sRow[t] = (int)((const long long*)ei_words)[e];
            sCol[t] = (int)((const long long*)ei_words)[(long long)E + e];
        } else {
            sRow[t] = ei_words[e];
            sCol[t] = ei_words[E + e];
        }
    }
    // --- folded BN scale/shift (includes b2) ---
    if (t >= 64 && t < 192) {
        int j = t - 64;
        float sc = bn_gamma[j] * rsqrtf(bn_var[j] + 1e-5f);
        sScale[j] = sc;
        sShift[j] = (b2[j] - bn_mean[j]) * sc + bn_beta[j];
    }
    // --- load edge_attr tile [64][32] ---
    {
        const float4* ea4 = (const float4*)edge_attr;
        #pragma unroll
        for (int i = 0; i < 2; i++) {
            int lin = t + i * 256;            // 0..511 float4s
            int e = lin >> 3, q = lin & 7;
            int ge = ebase + e; if (ge > E - 1) ge = E - 1;
            float4 v = ea4[(long long)ge * 8 + q];
            sEA[e][4*q+0] = v.x; sEA[e][4*q+1] = v.y;
            sEA[e][4*q+2] = v.z; sEA[e][4*q+3] = v.w;
        }
    }
    __syncthreads();

    float acc[8][4];
    #pragma unroll
    for (int i = 0; i < 8; i++) { acc[i][0]=0.f; acc[i][1]=0.f; acc[i][2]=0.f; acc[i][3]=0.f; }

    const float4* x4 = (const float4*)x;

    // ---- W2 GEMM in three K=128 chunks: x[row], x[col], e=tanh(ea@W1+b1) ----
    for (int ch = 0; ch < 3; ch++) {
        if (ch < 2) {
            const int* idx = (ch == 0) ? sRow : sCol;
            #pragma unroll
            for (int i = 0; i < 8; i++) {
                int lin = t + i * 256;        // 0..2047 float4s
                int e  = lin & 63;
                int kq = lin >> 6;            // 0..31
                float4 v = x4[(long long)idx[e] * 32 + kq];
                sAT[4*kq+0][e] = v.x; sAT[4*kq+1][e] = v.y;
                sAT[4*kq+2][e] = v.z; sAT[4*kq+3][e] = v.w;
            }
        } else {
            // compute e-tile: thread owns feature j, rows r0, r0+2, ...
            int j  = t & 127;
            int r0 = t >> 7;
            float w1r[32];
            #pragma unroll
            for (int k = 0; k < 32; k++) w1r[k] = W1[k * 128 + j];
            float bj = b1[j];
            #pragma unroll 1
            for (int r = r0; r < 64; r += 2) {
                float a = bj;
                #pragma unroll
                for (int k = 0; k < 32; k++) a += sEA[r][k] * w1r[k];
                sAT[j][r] = tanhf(a);
            }
        }
        __syncthreads();

        const float4* Wc = (const float4*)(W2 + ch * 128 * 128);
        #pragma unroll 4
        for (int k = 0; k < 128; k++) {
            float4 w = Wc[k * 32 + fg];
            #pragma unroll
            for (int i = 0; i < 8; i++) {
                float a = sAT[k][eg * 8 + i];   // warp-broadcast
                acc[i][0] += a * w.x; acc[i][1] += a * w.y;
                acc[i][2] += a * w.z; acc[i][3] += a * w.w;
            }
        }
        __syncthreads();
    }

    // ---- BN + ReLU -> sAT (transposed for second GEMM) ----
    {
        float sc[4], sh[4];
        #pragma unroll
        for (int c = 0; c < 4; c++) { sc[c] = sScale[fg*4+c]; sh[c] = sShift[fg*4+c]; }
        #pragma unroll
        for (int i = 0; i < 8; i++) {
            #pragma unroll
            for (int c = 0; c < 4; c++) {
                float h = acc[i][c] * sc[c] + sh[c];
                sAT[fg*4+c][eg*8+i] = fmaxf(h, 0.f);
            }
        }
    }
    __syncthreads();

    // ---- W3 GEMM ----
    float acc2[8][4];
    #pragma unroll
    for (int i = 0; i < 8; i++) { acc2[i][0]=0.f; acc2[i][1]=0.f; acc2[i][2]=0.f; acc2[i][3]=0.f; }

    const float4* W3v = (const float4*)W3;
    #pragma unroll 4
    for (int k = 0; k < 128; k++) {
        float4 w = W3v[k * 32 + fg];
        #pragma unroll
        for (int i = 0; i < 8; i++) {
            float a = sAT[k][eg * 8 + i];
            acc2[i][0] += a * w.x; acc2[i][1] += a * w.y;
            acc2[i][2] += a * w.z; acc2[i][3] += a * w.w;
        }
    }

    // ---- bias + ReLU + streaming store ----
    float4 bb = ((const float4*)b3)[fg];
    #pragma unroll
    for (int i = 0; i < 8; i++) {
        int e = ebase + eg * 8 + i;
        if (e < E) {
            float4 v;
            v.x = fmaxf(acc2[i][0] + bb.x, 0.f);
            v.y = fmaxf(acc2[i][1] + bb.y, 0.f);
            v.z = fmaxf(acc2[i][2] + bb.z, 0.f);
            v.w = fmaxf(acc2[i][3] + bb.w, 0.f);
            __stcs((float4*)(out + (long long)e * 128 + fg * 4), v);
        }
    }
}

extern "C" void kernel_launch(void* const* d_in, const int* in_sizes, int n_in,
                              void* d_out, int out_size) {
    const float* x         = (const float*)d_in[0];
    const int*   ei        = (const int*)  d_in[1];   // dtype probed in-kernel
    const float* edge_attr = (const float*)d_in[2];
    const float* W1        = (const float*)d_in[3];
    const float* b1        = (const float*)d_in[4];
    const float* W2        = (const float*)d_in[5];
    const float* b2        = (const float*)d_in[6];
    const float* bn_gamma  = (const float*)d_in[7];
    const float* bn_beta   = (const float*)d_in[8];
    const float* bn_mean   = (const float*)d_in[9];
    const float* bn_var    = (const float*)d_in[10];
    const float* W3        = (const float*)d_in[11];
    const float* b3        = (const float*)d_in[12];
    float* out = (float*)d_out;

    int E = in_sizes[2] / 32;                 // edge_attr is [E, 32]
    int blocks = (E + TILE_E - 1) / TILE_E;
    edge_model_kernel<<<blocks, 256>>>(x, ei, edge_attr, W1, b1, W2, b2,
                                       bn_gamma, bn_beta, bn_mean, bn_var,
                                       W3, b3, out, E);
}

// round 3
// speedup vs baseline: 1.5724x; 1.0022x over previous
#include <cuda_runtime.h>

// EdgeModel fused kernel (fp32 CUDA-core baseline, round 0)
// y = relu( relu(BN( [x[row]|x[col]|tanh(ea@W1+b1)] @ W2 + b2 )) @ W3 + b3 )
//
// Tile: 64 edges per block, 256 threads, thread tile 8 edges x 4 features.

#define TILE_E 64

__global__ __launch_bounds__(256) void edge_model_kernel(
    const float* __restrict__ x,
    const int* __restrict__ ei_words,   // edge_index as 32-bit words (dtype probed)
    const float* __restrict__ edge_attr,
    const float* __restrict__ W1, const float* __restrict__ b1,
    const float* __restrict__ W2, const float* __restrict__ b2,
    const float* __restrict__ bn_gamma, const float* __restrict__ bn_beta,
    const float* __restrict__ bn_mean, const float* __restrict__ bn_var,
    const float* __restrict__ W3, const float* __restrict__ b3,
    float* __restrict__ out, int E)
{
    __shared__ float sAT[128][65];   // staged A^T: [k][edge], scalar broadcast reads
    __shared__ float sEA[64][36];    // edge_attr tile
    __shared__ int   sRow[64], sCol[64];
    __shared__ float sScale[128], sShift[128];

    const int t  = threadIdx.x;
    const int fg = t & 31;    // feature group: features fg*4 .. fg*4+3
    const int eg = t >> 5;    // edge group: edges eg*8 .. eg*8+7
    const int ebase = blockIdx.x * TILE_E;

    // --- dtype probe: int64 edge_index has zero hi-words at odd positions ---
    const bool is64 = ((ei_words[1] | ei_words[3] | ei_words[5] | ei_words[7]) == 0);

    // --- load indices ---
    if (t < 64) {
        int e = ebase + t; if (e > E - 1) e = E - 1;
        if (is64) {
            sRow[t] = (int)((const long long*)ei_words)[e];
            sCol[t] = (int)((const long long*)ei_words)[(long long)E + e];
        } else {
            sRow[t] = ei_words[e];
            sCol[t] = ei_words[E + e];
        }
    }
    // --- folded BN scale/shift (includes b2) ---
    if (t >= 64 && t < 192) {
        int j = t - 64;
        float sc = bn_gamma[j] * rsqrtf(bn_var[j] + 1e-5f);
        sScale[j] = sc;
        sShift[j] = (b2[j] - bn_mean[j]) * sc + bn_beta[j];
    }
    // --- load edge_attr tile [64][32] ---
    {
        const float4* ea4 = (const float4*)edge_attr;
        #pragma unroll
        for (int i = 0; i < 2; i++) {
            int lin = t + i * 256;            // 0..511 float4s
            int e = lin >> 3, q = lin & 7;
            int ge = ebase + e; if (ge > E - 1) ge = E - 1;
            float4 v = ea4[(long long)ge * 8 + q];
            sEA[e][4*q+0] = v.x; sEA[e][4*q+1] = v.y;
            sEA[e][4*q+2] = v.z; sEA[e][4*q+3] = v.w;
        }
    }
    __syncthreads();

    float acc[8][4];
    #pragma unroll
    for (int i = 0; i < 8; i++) { acc[i][0]=0.f; acc[i][1]=0.f; acc[i][2]=0.f; acc[i][3]=0.f; }

    const float4* x4 = (const float4*)x;

    // ---- W2 GEMM in three K=128 chunks: x[row], x[col], e=tanh(ea@W1+b1) ----
    for (int ch = 0; ch < 3; ch++) {
        if (ch < 2) {
            const int* idx = (ch == 0) ? sRow : sCol;
            #pragma unroll
            for (int i = 0; i < 8; i++) {
                int lin = t + i * 256;        // 0..2047 float4s
                int e  = lin & 63;
                int kq = lin >> 6;            // 0..31
                float4 v = x4[(long long)idx[e] * 32 + kq];
                sAT[4*kq+0][e] = v.x; sAT[4*kq+1][e] = v.y;
                sAT[4*kq+2][e] = v.z; sAT[4*kq+3][e] = v.w;
            }
        } else {
            // compute e-tile: thread owns feature j, rows r0, r0+2, ...
            int j  = t & 127;
            int r0 = t >> 7;
            float w1r[32];
            #pragma unroll
            for (int k = 0; k < 32; k++) w1r[k] = W1[k * 128 + j];
            float bj = b1[j];
            #pragma unroll 1
            for (int r = r0; r < 64; r += 2) {
                float a = bj;
                #pragma unroll
                for (int k = 0; k < 32; k++) a += sEA[r][k] * w1r[k];
                sAT[j][r] = tanhf(a);
            }
        }
        __syncthreads();

        const float4* Wc = (const float4*)(W2 + ch * 128 * 128);
        #pragma unroll 4
        for (int k = 0; k < 128; k++) {
            float4 w = Wc[k * 32 + fg];
            #pragma unroll
            for (int i = 0; i < 8; i++) {
                float a = sAT[k][eg * 8 + i];   // warp-broadcast
                acc[i][0] += a * w.x; acc[i][1] += a * w.y;
                acc[i][2] += a * w.z; acc[i][3] += a * w.w;
            }
        }
        __syncthreads();
    }

    // ---- BN + ReLU -> sAT (transposed for second GEMM) ----
    {
        float sc[4], sh[4];
        #pragma unroll
        for (int c = 0; c < 4; c++) { sc[c] = sScale[fg*4+c]; sh[c] = sShift[fg*4+c]; }
        #pragma unroll
        for (int i = 0; i < 8; i++) {
            #pragma unroll
            for (int c = 0; c < 4; c++) {
                float h = acc[i][c] * sc[c] + sh[c];
                sAT[fg*4+c][eg*8+i] = fmaxf(h, 0.f);
            }
        }
    }
    __syncthreads();

    // ---- W3 GEMM ----
    float acc2[8][4];
    #pragma unroll
    for (int i = 0; i < 8; i++) { acc2[i][0]=0.f; acc2[i][1]=0.f; acc2[i][2]=0.f; acc2[i][3]=0.f; }

    const float4* W3v = (const float4*)W3;
    #pragma unroll 4
    for (int k = 0; k < 128; k++) {
        float4 w = W3v[k * 32 + fg];
        #pragma unroll
        for (int i = 0; i < 8; i++) {
            float a = sAT[k][eg * 8 + i];
            acc2[i][0] += a * w.x; acc2[i][1] += a * w.y;
            acc2[i][2] += a * w.z; acc2[i][3] += a * w.w;
        }
    }

    // ---- bias + ReLU + streaming store ----
    float4 bb = ((const float4*)b3)[fg];
    #pragma unroll
    for (int i = 0; i < 8; i++) {
        int e = ebase + eg * 8 + i;
        if (e < E) {
            float4 v;
            v.x = fmaxf(acc2[i][0] + bb.x, 0.f);
            v.y = fmaxf(acc2[i][1] + bb.y, 0.f);
            v.z = fmaxf(acc2[i][2] + bb.z, 0.f);
            v.w = fmaxf(acc2[i][3] + bb.w, 0.f);
            __stcs((float4*)(out + (long long)e * 128 + fg * 4), v);
        }
    }
}

extern "C" void kernel_launch(void* const* d_in, const int* in_sizes, int n_in,
                              void* d_out, int out_size) {
    const float* x         = (const float*)d_in[0];
    const int*   ei        = (const int*)  d_in[1];   // dtype probed in-kernel
    const float* edge_attr = (const float*)d_in[2];
    const float* W1        = (const float*)d_in[3];
    const float* b1        = (const float*)d_in[4];
    const float* W2        = (const float*)d_in[5];
    const float* b2        = (const float*)d_in[6];
    const float* bn_gamma  = (const float*)d_in[7];
    const float* bn_beta   = (const float*)d_in[8];
    const float* bn_mean   = (const float*)d_in[9];
    const float* bn_var    = (const float*)d_in[10];
    const float* W3        = (const float*)d_in[11];
    const float* b3        = (const float*)d_in[12];
    float* out = (float*)d_out;

    int E = in_sizes[2] / 32;                 // edge_attr is [E, 32]
    int blocks = (E + TILE_E - 1) / TILE_E;
    edge_model_kernel<<<blocks, 256>>>(x, ei, edge_attr, W1, b1, W2, b2,
                                       bn_gamma, bn_beta, bn_mean, bn_var,
                                       W3, b3, out, E);
}

// round 5
// speedup vs baseline: 3.6402x; 2.3151x over previous
#include <cuda_runtime.h>

#define NT 256
#define AS 132            // A smem row stride (floats)
#define WS 136            // W smem row stride (floats)
#define OFF_A   4096
#define OFF_W1  71680
#define OFF_W3  89088
#define OFF_W2  158720
#define SMEM_TOTAL 228352

#define CP16(dst, src)  asm volatile("cp.async.cg.shared.global [%0], [%1], 16;" :: "r"(dst), "l"(src) : "memory")
#define CP_COMMIT()     asm volatile("cp.async.commit_group;" ::: "memory")
#define CP_WAIT(n)      asm volatile("cp.async.wait_group %0;" :: "n"(n) : "memory")

__device__ __forceinline__ unsigned smem_u32(const void* p) {
    unsigned a;
    asm("{ .reg .u64 t; cvta.to.shared.u64 t, %1; cvt.u32.u64 %0, t; }" : "=r"(a) : "l"(p));
    return a;
}
__device__ __forceinline__ unsigned cvt_tf32(float f) {
    unsigned u; asm("cvt.rna.tf32.f32 %0, %1;" : "=r"(u) : "f"(f)); return u;
}
__device__ __forceinline__ void mma8(float* c, unsigned a0, unsigned a1, unsigned a2,
                                     unsigned a3, unsigned b0, unsigned b1) {
    asm volatile("mma.sync.aligned.m16n8k8.row.col.f32.tf32.tf32.f32 "
        "{%0,%1,%2,%3}, {%4,%5,%6,%7}, {%8,%9}, {%0,%1,%2,%3};"
        : "+f"(c[0]), "+f"(c[1]), "+f"(c[2]), "+f"(c[3])
        : "r"(a0), "r"(a1), "r"(a2), "r"(a3), "r"(b0), "r"(b1));
}
__device__ __forceinline__ float fast_tanh(float v) {
    float z, r;
    asm("ex2.approx.f32 %0, %1;" : "=f"(z) : "f"(fabsf(v) * -2.885390081777927f));
    asm("rcp.approx.f32 %0, %1;" : "=f"(r) : "f"(1.0f + z));
    return copysignf((1.0f - z) * r, v);
}
__device__ __forceinline__ void st_cs_v2(float* p, float a, float b) {
    asm volatile("st.global.cs.v2.f32 [%0], {%1,%2};" :: "l"(p), "f"(a), "f"(b) : "memory");
}

// per-warp fragment GEMM: C[32x64] += A[32xK] * B[Kx64]
// Abase = sA + (rbase+gid)*AS + tig ; Bbase = sW + tig*WS + cbase + gid
template<int KSTEPS>
__device__ __forceinline__ void gemm_frag(const float* __restrict__ Abase,
                                          const float* __restrict__ Bbase,
                                          float acc[2][8][4]) {
    #pragma unroll
    for (int ks = 0; ks < KSTEPS; ks++) {
        const float* Ak = Abase + ks * 8;
        const float* Bk = Bbase + ks * 8 * WS;
        unsigned a[2][4];
        #pragma unroll
        for (int mt = 0; mt < 2; mt++) {
            const float* Am = Ak + mt * 16 * AS;
            a[mt][0] = cvt_tf32(Am[0]);
            a[mt][1] = cvt_tf32(Am[8 * AS]);
            a[mt][2] = cvt_tf32(Am[4]);
            a[mt][3] = cvt_tf32(Am[8 * AS + 4]);
        }
        #pragma unroll
        for (int nt = 0; nt < 8; nt++) {
            unsigned b0 = cvt_tf32(Bk[nt * 8]);
            unsigned b1 = cvt_tf32(Bk[4 * WS + nt * 8]);
            mma8(acc[0][nt], a[0][0], a[0][1], a[0][2], a[0][3], b0, b1);
            mma8(acc[1][nt], a[1][0], a[1][1], a[1][2], a[1][3], b0, b1);
        }
    }
}

__global__ void __launch_bounds__(NT, 1)
edge_kernel(const float* __restrict__ x, const int* __restrict__ ei,
            const float* __restrict__ ea,
            const float* __restrict__ W1, const float* __restrict__ b1,
            const float* __restrict__ W2, const float* __restrict__ b2,
            const float* __restrict__ gamma, const float* __restrict__ beta,
            const float* __restrict__ mean, const float* __restrict__ var,
            const float* __restrict__ W3, const float* __restrict__ b3,
            float* __restrict__ out, int E, int ntiles)
{
    extern __shared__ char smem[];
    const unsigned sb = smem_u32(smem);
    int*   sRow   = (int*)(smem);
    int*   sCol   = (int*)(smem + 512);
    float* sScale = (float*)(smem + 1024);
    float* sShift = (float*)(smem + 1536);
    float* sB1    = (float*)(smem + 2048);
    float* sB3    = (float*)(smem + 2560);
    float* sA  = (float*)(smem + OFF_A);
    float* sW1 = (float*)(smem + OFF_W1);
    float* sW3 = (float*)(smem + OFF_W3);
    float* sW2 = (float*)(smem + OFF_W2);

    const int tid = threadIdx.x;
    const int w = tid >> 5, lane = tid & 31;
    const int gid = lane >> 2, tig = lane & 3;
    const int rbase = (w >> 1) * 32;        // warp row block
    const int cbase = (w & 1) * 64;         // warp col block
    const int rw = tid >> 1, hf = tid & 1;  // cp.async row / half

    // ---- once: constants + resident W1, W3 ----
    if (tid < 128) {
        float sc = gamma[tid] * rsqrtf(var[tid] + 1e-5f);
        sScale[tid] = sc;
        sShift[tid] = (b2[tid] - mean[tid]) * sc + beta[tid];
        sB1[tid] = b1[tid];
        sB3[tid] = b3[tid];
    }
    {
        int r1 = tid >> 3, p = tid & 7;     // W1: 32 rows, 8 threads/row
        const float* s = W1 + r1 * 128 + p * 16;
        unsigned d = sb + OFF_W1 + (unsigned)(r1 * WS + p * 16) * 4;
        #pragma unroll
        for (int i = 0; i < 4; i++) CP16(d + i * 16, s + i * 4);
        const float* s3 = W3 + rw * 128 + hf * 64;
        unsigned d3 = sb + OFF_W3 + (unsigned)(rw * WS + hf * 64) * 4;
        #pragma unroll
        for (int i = 0; i < 16; i++) CP16(d3 + i * 16, s3 + i * 4);
        CP_COMMIT();
    }
    CP_WAIT(0);
    __syncthreads();

    const bool is64 = ((ei[1] | ei[3] | ei[5] | ei[7]) == 0);
    const long long* ei64 = (const long long*)ei;

    const float* Ath = sA + (rbase + gid) * AS + tig;        // per-thread frag bases
    const float* W1th = sW1 + tig * WS + cbase + gid;
    const float* W2th = sW2 + tig * WS + cbase + gid;
    const float* W3th = sW3 + tig * WS + cbase + gid;

    for (int tile = blockIdx.x; tile < ntiles; tile += gridDim.x) {
        const int ebase = tile * 128;

        // prefetch EA -> A[k<32]   (group, then W2 chunk2 group)
        {
            int ge = min(ebase + rw, E - 1);
            const float* s = ea + (long long)ge * 32 + hf * 16;
            unsigned d = sb + OFF_A + (unsigned)(rw * AS + hf * 16) * 4;
            #pragma unroll
            for (int i = 0; i < 4; i++) CP16(d + i * 16, s + i * 4);
            CP_COMMIT();
            const float* s2 = W2 + (256 + rw) * 128 + hf * 64;
            unsigned d2 = sb + OFF_W2 + (unsigned)(rw * WS + hf * 64) * 4;
            #pragma unroll
            for (int i = 0; i < 16; i++) CP16(d2 + i * 16, s2 + i * 4);
            CP_COMMIT();
        }
        if (tid < 128) {
            int e = min(ebase + tid, E - 1);
            sRow[tid] = is64 ? (int)ei64[e] : ei[e];
        } else {
            int e = min(ebase + tid - 128, E - 1);
            sCol[tid - 128] = is64 ? (int)ei64[(long long)E + e] : ei[E + e];
        }
        CP_WAIT(1);                 // EA in
        __syncthreads();

        // ---- MMA1: e = EA @ W1  (K=32) ----
        float eacc[2][8][4];
        #pragma unroll
        for (int mt = 0; mt < 2; mt++)
            #pragma unroll
            for (int nt = 0; nt < 8; nt++)
                { eacc[mt][nt][0]=0.f; eacc[mt][nt][1]=0.f; eacc[mt][nt][2]=0.f; eacc[mt][nt][3]=0.f; }
        gemm_frag<4>(Ath, W1th, eacc);
        __syncthreads();            // everyone done reading EA

        // epilogue1: tanh(e + b1) -> A
        #pragma unroll
        for (int mt = 0; mt < 2; mt++) {
            int r = rbase + mt * 16 + gid;
            #pragma unroll
            for (int nt = 0; nt < 8; nt++) {
                int c = cbase + nt * 8 + 2 * tig;
                float bb0 = sB1[c], bb1 = sB1[c + 1];
                float* p0 = sA + r * AS + c;
                p0[0] = fast_tanh(eacc[mt][nt][0] + bb0);
                p0[1] = fast_tanh(eacc[mt][nt][1] + bb1);
                float* p1 = sA + (r + 8) * AS + c;
                p1[0] = fast_tanh(eacc[mt][nt][2] + bb0);
                p1[1] = fast_tanh(eacc[mt][nt][3] + bb1);
            }
        }
        CP_WAIT(0);                 // W2c2 in
        __syncthreads();

        // ---- MMA2a: h = e @ W2c2 ----
        float hacc[2][8][4];
        #pragma unroll
        for (int mt = 0; mt < 2; mt++)
            #pragma unroll
            for (int nt = 0; nt < 8; nt++)
                { hacc[mt][nt][0]=0.f; hacc[mt][nt][1]=0.f; hacc[mt][nt][2]=0.f; hacc[mt][nt][3]=0.f; }
        gemm_frag<16>(Ath, W2th, hacc);
        __syncthreads();            // A, W2buf free

        // gather x[row] -> A ; W2c0 -> W2buf
        {
            const float* s = x + (long long)sRow[rw] * 128 + hf * 64;
            unsigned d = sb + OFF_A + (unsigned)(rw * AS + hf * 64) * 4;
            #pragma unroll
            for (int i = 0; i < 16; i++) CP16(d + i * 16, s + i * 4);
            const float* s2 = W2 + rw * 128 + hf * 64;
            unsigned d2 = sb + OFF_W2 + (unsigned)(rw * WS + hf * 64) * 4;
            #pragma unroll
            for (int i = 0; i < 16; i++) CP16(d2 + i * 16, s2 + i * 4);
            CP_COMMIT();
        }
        CP_WAIT(0);
        __syncthreads();

        // ---- MMA2b: h += x_row @ W2c0 ----
        gemm_frag<16>(Ath, W2th, hacc);
        __syncthreads();

        // gather x[col] -> A ; W2c1 -> W2buf
        {
            const float* s = x + (long long)sCol[rw] * 128 + hf * 64;
            unsigned d = sb + OFF_A + (unsigned)(rw * AS + hf * 64) * 4;
            #pragma unroll
            for (int i = 0; i < 16; i++) CP16(d + i * 16, s + i * 4);
            const float* s2 = W2 + (128 + rw) * 128 + hf * 64;
            unsigned d2 = sb + OFF_W2 + (unsigned)(rw * WS + hf * 64) * 4;
            #pragma unroll
            for (int i = 0; i < 16; i++) CP16(d2 + i * 16, s2 + i * 4);
            CP_COMMIT();
        }
        CP_WAIT(0);
        __syncthreads();

        // ---- MMA2c: h += x_col @ W2c1 ----
        gemm_frag<16>(Ath, W2th, hacc);
        __syncthreads();            // A free for h

        // epilogue2: h = relu(h*scale + shift) -> A
        #pragma unroll
        for (int mt = 0; mt < 2; mt++) {
            int r = rbase + mt * 16 + gid;
            #pragma unroll
            for (int nt = 0; nt < 8; nt++) {
                int c = cbase + nt * 8 + 2 * tig;
                float sc0 = sScale[c], sc1 = sScale[c + 1];
                float sh0 = sShift[c], sh1 = sShift[c + 1];
                float* p0 = sA + r * AS + c;
                p0[0] = fmaxf(fmaf(hacc[mt][nt][0], sc0, sh0), 0.f);
                p0[1] = fmaxf(fmaf(hacc[mt][nt][1], sc1, sh1), 0.f);
                float* p1 = sA + (r + 8) * AS + c;
                p1[0] = fmaxf(fmaf(hacc[mt][nt][2], sc0, sh0), 0.f);
                p1[1] = fmaxf(fmaf(hacc[mt][nt][3], sc1, sh1), 0.f);
            }
        }
        __syncthreads();

        // ---- MMA3: y = h @ W3 ----
        float yacc[2][8][4];
        #pragma unroll
        for (int mt = 0; mt < 2; mt++)
            #pragma unroll
            for (int nt = 0; nt < 8; nt++)
                { yacc[mt][nt][0]=0.f; yacc[mt][nt][1]=0.f; yacc[mt][nt][2]=0.f; yacc[mt][nt][3]=0.f; }
        gemm_frag<16>(Ath, W3th, yacc);

        // epilogue3: relu(y + b3) -> gmem (streaming)
        #pragma unroll
        for (int mt = 0; mt < 2; mt++) {
            int r = rbase + mt * 16 + gid;
            int e0 = ebase + r, e1 = e0 + 8;
            float* po0 = out + (long long)e0 * 128;
            float* po1 = out + (long long)e1 * 128;
            #pragma unroll
            for (int nt = 0; nt < 8; nt++) {
                int c = cbase + nt * 8 + 2 * tig;
                float bb0 = sB3[c], bb1 = sB3[c + 1];
                if (e0 < E)
                    st_cs_v2(po0 + c, fmaxf(yacc[mt][nt][0] + bb0, 0.f),
                                      fmaxf(yacc[mt][nt][1] + bb1, 0.f));
                if (e1 < E)
                    st_cs_v2(po1 + c, fmaxf(yacc[mt][nt][2] + bb0, 0.f),
                                      fmaxf(yacc[mt][nt][3] + bb1, 0.f));
            }
        }
        __syncthreads();            // A free for next tile's EA prefetch
    }
}

extern "C" void kernel_launch(void* const* d_in, const int* in_sizes, int n_in,
                              void* d_out, int out_size) {
    const float* x     = (const float*)d_in[0];
    const int*   ei    = (const int*)  d_in[1];
    const float* eattr = (const float*)d_in[2];
    const float* W1    = (const float*)d_in[3];
    const float* b1    = (const float*)d_in[4];
    const float* W2    = (const float*)d_in[5];
    const float* b2    = (const float*)d_in[6];
    const float* gam   = (const float*)d_in[7];
    const float* bet   = (const float*)d_in[8];
    const float* mean  = (const float*)d_in[9];
    const float* var   = (const float*)d_in[10];
    const float* W3    = (const float*)d_in[11];
    const float* b3    = (const float*)d_in[12];
    float* out = (float*)d_out;

    int E = in_sizes[2] / 32;
    int ntiles = (E + 127) / 128;

    static int configured = 0;
    cudaFuncSetAttribute(edge_kernel, cudaFuncAttributeMaxDynamicSharedMemorySize, SMEM_TOTAL);
    (void)configured;

    edge_kernel<<<148, NT, SMEM_TOTAL>>>(x, ei, eattr, W1, b1, W2, b2,
                                         gam, bet, mean, var, W3, b3,
                                         out, E, ntiles);
}

// round 6
// speedup vs baseline: 3.7789x; 1.0381x over previous
#include <cuda_runtime.h>

#define NT 256
#define AS 132                      // A smem row stride (floats)

// ---- smem layout (bytes) ----
#define OFF_IDX   0                 // sRow0,sCol0,sRow1,sCol1 : 4*512
#define OFF_SC    2048              // scale,shift,b1,b3 : 4*512
#define OFF_A0    4096              // 128*132*4 = 67584
#define OFF_A1    71680             // 67584
#define OFF_W1    139264            // 16384 (frag-major W1)
#define OFF_H0    155648            // 32768 (frag-major half-chunk)
#define OFF_H1    188416            // 32768
#define SMEM_TOTAL 221184

// frag-major weight scratch (pre-rounded to tf32)
__device__ __align__(16) float g_W1f[4096];        // 4 ksteps
__device__ __align__(16) float g_W2f[6 * 8192];    // [chunk*2+half][8192]
__device__ __align__(16) float g_W3f[2 * 8192];    // [half][8192]

#define CP16(dst, src)  asm volatile("cp.async.cg.shared.global [%0], [%1], 16;" :: "r"(dst), "l"(src) : "memory")
#define CP_COMMIT()     asm volatile("cp.async.commit_group;" ::: "memory")
#define CP_WAIT(n)      asm volatile("cp.async.wait_group %0;" :: "n"(n) : "memory")

__device__ __forceinline__ unsigned smem_u32(const void* p) {
    unsigned a;
    asm("{ .reg .u64 t; cvta.to.shared.u64 t, %1; cvt.u32.u64 %0, t; }" : "=r"(a) : "l"(p));
    return a;
}
__device__ __forceinline__ unsigned cvt_tf32(float f) {
    unsigned u; asm("cvt.rna.tf32.f32 %0, %1;" : "=r"(u) : "f"(f)); return u;
}
__device__ __forceinline__ float rndf(float f) { return __uint_as_float(cvt_tf32(f)); }
__device__ __forceinline__ void mma8(float* c, unsigned a0, unsigned a1, unsigned a2,
                                     unsigned a3, unsigned b0, unsigned b1) {
    asm volatile("mma.sync.aligned.m16n8k8.row.col.f32.tf32.tf32.f32 "
        "{%0,%1,%2,%3}, {%4,%5,%6,%7}, {%8,%9}, {%0,%1,%2,%3};"
        : "+f"(c[0]), "+f"(c[1]), "+f"(c[2]), "+f"(c[3])
        : "r"(a0), "r"(a1), "r"(a2), "r"(a3), "r"(b0), "r"(b1));
}
__device__ __forceinline__ float fast_tanh(float v) {
    float z, r;
    asm("ex2.approx.f32 %0, %1;" : "=f"(z) : "f"(fabsf(v) * -2.885390081777927f));
    asm("rcp.approx.f32 %0, %1;" : "=f"(r) : "f"(1.0f + z));
    return copysignf((1.0f - z) * r, v);
}
__device__ __forceinline__ void st_cs_v2(float* p, float a, float b) {
    asm volatile("st.global.cs.v2.f32 [%0], {%1,%2};" :: "l"(p), "f"(a), "f"(b) : "memory");
}

// GEMM segment: acc[2][8][4] += A[32 x 8*KS] * Bfrag (frag-major, conflict-free LDS.64)
template<int KS, bool CVT>
__device__ __forceinline__ void gemm_seg(const float* __restrict__ Ath,
                                         const float2* __restrict__ Bth,
                                         float acc[2][8][4]) {
    #pragma unroll
    for (int ks = 0; ks < KS; ks++) {
        const float* Ak = Ath + ks * 8;
        unsigned a[2][4];
        #pragma unroll
        for (int mt = 0; mt < 2; mt++) {
            const float* Am = Ak + mt * 16 * AS;
            float f0 = Am[0], f1 = Am[8 * AS], f2 = Am[4], f3 = Am[8 * AS + 4];
            if (CVT) {
                a[mt][0] = cvt_tf32(f0); a[mt][1] = cvt_tf32(f1);
                a[mt][2] = cvt_tf32(f2); a[mt][3] = cvt_tf32(f3);
            } else {
                a[mt][0] = __float_as_uint(f0); a[mt][1] = __float_as_uint(f1);
                a[mt][2] = __float_as_uint(f2); a[mt][3] = __float_as_uint(f3);
            }
        }
        const float2* Bk = Bth + ks * 512;         // (ks*2+cb) blocks of 512 floats
        #pragma unroll
        for (int nt = 0; nt < 8; nt++) {
            float2 b = Bk[nt * 32];
            unsigned b0 = __float_as_uint(b.x), b1 = __float_as_uint(b.y);
            mma8(acc[0][nt], a[0][0], a[0][1], a[0][2], a[0][3], b0, b1);
            mma8(acc[1][nt], a[1][0], a[1][1], a[1][2], a[1][3], b0, b1);
        }
    }
}

// ---- prep: permute + rna-round weights into fragment-major scratch ----
// dest index d decode: wh=d&1 l=(d>>1)&31 nt=(d>>6)&7 cb=(d>>9)&1 ks=d>>10
__global__ void prep_frag(const float* __restrict__ W1,
                          const float* __restrict__ W2,
                          const float* __restrict__ W3) {
    int t = blockIdx.x * blockDim.x + threadIdx.x;
    int stride = gridDim.x * blockDim.x;
    for (int d = t; d < 4096; d += stride) {
        int wh = d & 1, l = (d >> 1) & 31, nt = (d >> 6) & 7, cb = (d >> 9) & 1, ks = d >> 10;
        int k = ks * 8 + (l & 3) + wh * 4, n = cb * 64 + nt * 8 + (l >> 2);
        g_W1f[d] = rndf(W1[k * 128 + n]);
    }
    for (int i = t; i < 6 * 8192; i += stride) {
        int hh = i >> 13, d = i & 8191;
        int wh = d & 1, l = (d >> 1) & 31, nt = (d >> 6) & 7, cb = (d >> 9) & 1, ks = d >> 10;
        int k = (hh >> 1) * 128 + (hh & 1) * 64 + ks * 8 + (l & 3) + wh * 4;
        int n = cb * 64 + nt * 8 + (l >> 2);
        g_W2f[i] = rndf(W2[k * 128 + n]);
    }
    for (int i = t; i < 2 * 8192; i += stride) {
        int hh = i >> 13, d = i & 8191;
        int wh = d & 1, l = (d >> 1) & 31, nt = (d >> 6) & 7, cb = (d >> 9) & 1, ks = d >> 10;
        int k = hh * 64 + ks * 8 + (l & 3) + wh * 4;
        int n = cb * 64 + nt * 8 + (l >> 2);
        g_W3f[i] = rndf(W3[k * 128 + n]);
    }
}

#define ZERO_ACC(acc) { _Pragma("unroll") for (int _m = 0; _m < 2; _m++) \
    _Pragma("unroll") for (int _n = 0; _n < 8; _n++) { \
        (acc)[_m][_n][0]=0.f;(acc)[_m][_n][1]=0.f;(acc)[_m][_n][2]=0.f;(acc)[_m][_n][3]=0.f; } }

__global__ void __launch_bounds__(NT, 1)
edge_kernel(const float* __restrict__ x, const int* __restrict__ ei,
            const float* __restrict__ ea,
            const float* __restrict__ b1, const float* __restrict__ b2,
            const float* __restrict__ gamma, const float* __restrict__ beta,
            const float* __restrict__ mean, const float* __restrict__ var,
            const float* __restrict__ b3,
            float* __restrict__ out, int E, int ntiles)
{
    extern __shared__ char smem[];
    const unsigned sb = smem_u32(smem);
    int*   sIdx   = (int*)(smem + OFF_IDX);          // [4][128]: row0,col0,row1,col1
    float* sScale = (float*)(smem + OFF_SC);
    float* sShift = (float*)(smem + OFF_SC + 512);
    float* sB1    = (float*)(smem + OFF_SC + 1024);
    float* sB3    = (float*)(smem + OFF_SC + 1536);
    float* sA0 = (float*)(smem + OFF_A0);
    float* sA1 = (float*)(smem + OFF_A1);

    const int tid = threadIdx.x;
    const int w = tid >> 5, lane = tid & 31;
    const int gid = lane >> 2, tig = lane & 3;
    const int rbase = (w >> 1) * 32, cb = w & 1, cbase = cb * 64;
    const int rw = tid >> 1, hf = tid & 1;

    if (tid < 128) {
        float sc = gamma[tid] * rsqrtf(var[tid] + 1e-5f);
        sScale[tid] = sc;
        sShift[tid] = (b2[tid] - mean[tid]) * sc + beta[tid];
        sB1[tid] = b1[tid];
        sB3[tid] = b3[tid];
    }
    // resident W1 frag (16KB, linear copy)
    {
        const float* s = g_W1f + tid * 16;
        unsigned d = sb + OFF_W1 + tid * 64;
        #pragma unroll
        for (int i = 0; i < 4; i++) CP16(d + i * 16, s + i * 4);
        CP_COMMIT();
    }
    CP_WAIT(0);
    __syncthreads();

    const bool is64 = ((ei[1] | ei[3] | ei[5] | ei[7]) == 0);
    const long long* ei64 = (const long long*)ei;

    const float* A0th = sA0 + (rbase + gid) * AS + tig;
    const float* A1th = sA1 + (rbase + gid) * AS + tig;
    const float2* W1th = (const float2*)(smem + OFF_W1) + cb * 256 + lane;
    const float2* H0th = (const float2*)(smem + OFF_H0) + cb * 256 + lane;
    const float2* H1th = (const float2*)(smem + OFF_H1) + cb * 256 + lane;

    // ---- load helpers (all 256 threads participate; each issue = 1 group) ----
    #define LOAD_W(OFF, srcbase) { \
        const float* _s = (srcbase) + tid * 32; \
        unsigned _d = sb + (OFF) + tid * 128; \
        _Pragma("unroll") for (int _i = 0; _i < 8; _i++) CP16(_d + _i * 16, _s + _i * 4); \
        CP_COMMIT(); }
    #define LOAD_EA(OFF, eb) { \
        int _ge = min((eb) + rw, E - 1); \
        const float* _s = ea + (long long)_ge * 32 + hf * 16; \
        unsigned _d = sb + (OFF) + (unsigned)(rw * AS + hf * 16) * 4; \
        _Pragma("unroll") for (int _i = 0; _i < 4; _i++) CP16(_d + _i * 16, _s + _i * 4); \
        CP_COMMIT(); }
    #define LOAD_X(OFF, idxp) { \
        const float* _s = x + (long long)(idxp)[rw] * 128 + hf * 64; \
        unsigned _d = sb + (OFF) + (unsigned)(rw * AS + hf * 64) * 4; \
        _Pragma("unroll") for (int _i = 0; _i < 16; _i++) CP16(_d + _i * 16, _s + _i * 4); \
        CP_COMMIT(); }
    #define LOAD_IDX(dstR, dstC, eb) { \
        if (tid < 128) { int _e = min((eb) + tid, E - 1); \
            (dstR)[tid] = is64 ? (int)ei64[_e] : ei[_e]; \
        } else { int _e = min((eb) + tid - 128, E - 1); \
            (dstC)[tid - 128] = is64 ? (int)ei64[(long long)E + _e] : ei[E + _e]; } }

    int pp = 0;
    const int tile0 = blockIdx.x;
    if (tile0 < ntiles) {
        LOAD_IDX(sIdx, sIdx + 128, tile0 * 128);
        __syncthreads();
        LOAD_EA(OFF_A0, tile0 * 128);         // g: EA
        LOAD_W(OFF_H0, g_W2f + 4 * 8192);     // g: c2H0
        LOAD_W(OFF_H1, g_W2f + 5 * 8192);     // g: c2H1
        LOAD_X(OFF_A1, sIdx);                 // g: xrow
    }

    for (int tile = tile0; tile < ntiles; tile += gridDim.x) {
        const int ebase = tile * 128;
        int* curRow = sIdx + pp * 256;
        int* curCol = curRow + 128;
        int* nxtRow = sIdx + (pp ^ 1) * 256;
        int* nxtCol = nxtRow + 128;
        int nxt = tile + gridDim.x;
        int nebase = (nxt < ntiles ? nxt : tile) * 128;

        float acc[2][8][4];

        // MMA1: e = EA @ W1
        CP_WAIT(3); __syncthreads();
        ZERO_ACC(acc);
        gemm_seg<4, true>(A0th, W1th, acc);
        __syncthreads();
        // epi1: tanh -> A0 (pre-rounded)
        #pragma unroll
        for (int mt = 0; mt < 2; mt++) {
            int r = rbase + mt * 16 + gid;
            #pragma unroll
            for (int nt = 0; nt < 8; nt++) {
                int c = cbase + nt * 8 + 2 * tig;
                float bb0 = sB1[c], bb1 = sB1[c + 1];
                *(float2*)(sA0 + r * AS + c) = make_float2(
                    rndf(fast_tanh(acc[0][nt][0] + bb0)), rndf(fast_tanh(acc[0][nt][1] + bb1)));
                *(float2*)(sA0 + (r + 8) * AS + c) = make_float2(
                    rndf(fast_tanh(acc[0][nt][2] + bb0)), rndf(fast_tanh(acc[0][nt][3] + bb1)));
                acc[0][nt][0] = acc[1][nt][0]; acc[0][nt][1] = acc[1][nt][1];
                acc[0][nt][2] = acc[1][nt][2]; acc[0][nt][3] = acc[1][nt][3];
            }
            if (mt == 0) { int r2 = rbase + 16 + gid; (void)r2; }
        }
        float hacc[2][8][4];
        ZERO_ACC(hacc);

        CP_WAIT(2); __syncthreads();                          // c2H0 in; epi1 visible
        gemm_seg<8, false>(A0th, H0th, hacc);                 // e[0:64] @ c2H0
        __syncthreads();
        LOAD_W(OFF_H0, g_W2f + 0 * 8192);                     // g: c0H0
        CP_WAIT(2); __syncthreads();                          // c2H1 in
        gemm_seg<8, false>(A0th + 64, H1th, hacc);            // e[64:128] @ c2H1
        __syncthreads();
        LOAD_W(OFF_H1, g_W2f + 1 * 8192);                     // g: c0H1
        LOAD_X(OFF_A0, curCol);                               // g: xcol
        CP_WAIT(2); __syncthreads();                          // xrow + c0H0 in
        gemm_seg<8, true>(A1th, H0th, hacc);                  // xr[0:64] @ c0H0
        __syncthreads();
        LOAD_W(OFF_H0, g_W2f + 2 * 8192);                     // g: c1H0
        CP_WAIT(2); __syncthreads();                          // c0H1 in
        gemm_seg<8, true>(A1th + 64, H1th, hacc);             // xr[64:128] @ c0H1
        __syncthreads();
        LOAD_W(OFF_H1, g_W2f + 3 * 8192);                     // g: c1H1
        CP_WAIT(1); __syncthreads();                          // xcol + c1H0 in
        gemm_seg<8, true>(A0th, H0th, hacc);                  // xc[0:64] @ c1H0
        __syncthreads();
        LOAD_W(OFF_H0, g_W3f + 0 * 8192);                     // g: w3H0
        CP_WAIT(1); __syncthreads();                          // c1H1 in
        gemm_seg<8, true>(A0th + 64, H1th, hacc);             // xc[64:128] @ c1H1
        __syncthreads();

        // epi2: h = relu(BN) -> A1 (pre-rounded); prefetch next indices
        #pragma unroll
        for (int mt = 0; mt < 2; mt++) {
            int r = rbase + mt * 16 + gid;
            #pragma unroll
            for (int nt = 0; nt < 8; nt++) {
                int c = cbase + nt * 8 + 2 * tig;
                float sc0 = sScale[c], sc1 = sScale[c + 1];
                float sh0 = sShift[c], sh1 = sShift[c + 1];
                *(float2*)(sA1 + r * AS + c) = make_float2(
                    rndf(fmaxf(fmaf(hacc[mt][nt][0], sc0, sh0), 0.f)),
                    rndf(fmaxf(fmaf(hacc[mt][nt][1], sc1, sh1), 0.f)));
                *(float2*)(sA1 + (r + 8) * AS + c) = make_float2(
                    rndf(fmaxf(fmaf(hacc[mt][nt][2], sc0, sh0), 0.f)),
                    rndf(fmaxf(fmaf(hacc[mt][nt][3], sc1, sh1), 0.f)));
            }
        }
        LOAD_IDX(nxtRow, nxtCol, nebase);
        LOAD_W(OFF_H1, g_W3f + 1 * 8192);                     // g: w3H1
        LOAD_EA(OFF_A0, nebase);                              // g: EA'
        CP_WAIT(2); __syncthreads();                          // w3H0 in; epi2+idx visible

        float yacc[2][8][4];
        ZERO_ACC(yacc);
        gemm_seg<8, false>(A1th, H0th, yacc);                 // h[0:64] @ w3H0
        __syncthreads();
        LOAD_W(OFF_H0, g_W2f + 4 * 8192);                     // g: c2'H0
        CP_WAIT(2); __syncthreads();                          // w3H1 in
        gemm_seg<8, false>(A1th + 64, H1th, yacc);            // h[64:128] @ w3H1

        // epi3: relu(y + b3) -> gmem
        #pragma unroll
        for (int mt = 0; mt < 2; mt++) {
            int r = rbase + mt * 16 + gid;
            int e0 = ebase + r, e1 = e0 + 8;
            float* po0 = out + (long long)e0 * 128;
            float* po1 = out + (long long)e1 * 128;
            #pragma unroll
            for (int nt = 0; nt < 8; nt++) {
                int c = cbase + nt * 8 + 2 * tig;
                float bb0 = sB3[c], bb1 = sB3[c + 1];
                if (e0 < E)
                    st_cs_v2(po0 + c, fmaxf(yacc[mt][nt][0] + bb0, 0.f),
                                      fmaxf(yacc[mt][nt][1] + bb1, 0.f));
                if (e1 < E)
                    st_cs_v2(po1 + c, fmaxf(yacc[mt][nt][2] + bb0, 0.f),
                                      fmaxf(yacc[mt][nt][3] + bb1, 0.f));
            }
        }
        __syncthreads();                                      // H1/A1 readers done
        LOAD_W(OFF_H1, g_W2f + 5 * 8192);                     // g: c2'H1
        LOAD_X(OFF_A1, nxtRow);                               // g: xrow'
        pp ^= 1;
    }
    CP_WAIT(0);
    __syncthreads();
}

extern "C" void kernel_launch(void* const* d_in, const int* in_sizes, int n_in,
                              void* d_out, int out_size) {
    const float* x     = (const float*)d_in[0];
    const int*   ei    = (const int*)  d_in[1];
    const float* eattr = (const float*)d_in[2];
    const float* W1    = (const float*)d_in[3];
    const float* b1    = (const float*)d_in[4];
    const float* W2    = (const float*)d_in[5];
    const float* b2    = (const float*)d_in[6];
    const float* gam   = (const float*)d_in[7];
    const float* bet   = (const float*)d_in[8];
    const float* mean  = (const float*)d_in[9];
    const float* var   = (const float*)d_in[10];
    const float* W3    = (const float*)d_in[11];
    const float* b3    = (const float*)d_in[12];
    float* out = (float*)d_out;

    int E = in_sizes[2] / 32;
    int ntiles = (E + 127) / 128;

    cudaFuncSetAttribute(edge_kernel, cudaFuncAttributeMaxDynamicSharedMemorySize, SMEM_TOTAL);

    prep_frag<<<64, 256>>>(W1, W2, W3);
    edge_kernel<<<148, NT, SMEM_TOTAL>>>(x, ei, eattr, b1, b2, gam, bet,
                                         mean, var, b3, out, E, ntiles);
}

// round 7
// speedup vs baseline: 6.9993x; 1.8522x over previous
#include <cuda_runtime.h>

#define NT 256

// ---- smem layout (bytes) ----
#define OFF_IDX  0        // 2 x (64 row + 64 col) ints = 1024
#define OFF_SC   1024     // scale,shift,b1,b3 : 4*512 = 2048
#define OFF_EAF  3072     // EA fp32 staging 64x32x4 = 8192
#define OFF_A0   11264    // 64 rows x 136 halfs x 2B = 17408
#define OFF_A1   28672    // 17408
#define OFF_WB0  46080    // 16384
#define OFF_WB1  62464    // 16384
#define OFF_WB2  78848    // 16384
#define SMEM_TOTAL 95232

#define ARB 272           // A row stride bytes (136 halfs)

// ---- device scratch (static: no runtime allocs) ----
__device__ __align__(16) unsigned g_xh[131072 * 64];   // x as fp16x2 (capacity 131072 nodes)
__device__ __align__(16) uint2 g_W1h[2 * 512];         // 2 ksteps
__device__ __align__(16) uint2 g_W2h[24 * 512];        // 24 ksteps
__device__ __align__(16) uint2 g_W3h[8 * 512];         // 8 ksteps

#define CP16(dst, src)  asm volatile("cp.async.cg.shared.global [%0], [%1], 16;" :: "r"(dst), "l"(src) : "memory")
#define CP_COMMIT()     asm volatile("cp.async.commit_group;" ::: "memory")
#define CP_WAIT(n)      asm volatile("cp.async.wait_group %0;" :: "n"(n) : "memory")

__device__ __forceinline__ unsigned smem_u32(const void* p) {
    unsigned a;
    asm("{ .reg .u64 t; cvta.to.shared.u64 t, %1; cvt.u32.u64 %0, t; }" : "=r"(a) : "l"(p));
    return a;
}
// pack two fp32 -> fp16x2 (lo = first arg)
__device__ __forceinline__ unsigned f22h2(float lo, float hi) {
    unsigned r;
    asm("cvt.rn.f16x2.f32 %0, %1, %2;" : "=r"(r) : "f"(hi), "f"(lo));
    return r;
}
__device__ __forceinline__ void mma16(float* c, unsigned a0, unsigned a1, unsigned a2,
                                      unsigned a3, unsigned b0, unsigned b1) {
    asm volatile("mma.sync.aligned.m16n8k16.row.col.f32.f16.f16.f32 "
        "{%0,%1,%2,%3}, {%4,%5,%6,%7}, {%8,%9}, {%0,%1,%2,%3};"
        : "+f"(c[0]), "+f"(c[1]), "+f"(c[2]), "+f"(c[3])
        : "r"(a0), "r"(a1), "r"(a2), "r"(a3), "r"(b0), "r"(b1));
}
__device__ __forceinline__ float fast_tanh(float v) {
    float z, r;
    asm("ex2.approx.f32 %0, %1;" : "=f"(z) : "f"(fabsf(v) * -2.885390081777927f));
    asm("rcp.approx.f32 %0, %1;" : "=f"(r) : "f"(1.0f + z));
    return copysignf((1.0f - z) * r, v);
}
__device__ __forceinline__ void st_cs_v2(float* p, float a, float b) {
    asm volatile("st.global.cs.v2.f32 [%0], {%1,%2};" :: "l"(p), "f"(a), "f"(b) : "memory");
}

// warp GEMM segment: acc[8][4] += A[16 x 16*KS] * W(frag-major)
template<int KS>
__device__ __forceinline__ void seg16(const char* Ab, const uint2* Wt, float acc[8][4]) {
    #pragma unroll
    for (int ks = 0; ks < KS; ks++) {
        unsigned a0 = *(const unsigned*)(Ab + ks * 32);
        unsigned a1 = *(const unsigned*)(Ab + ks * 32 + 8 * ARB);
        unsigned a2 = *(const unsigned*)(Ab + ks * 32 + 16);
        unsigned a3 = *(const unsigned*)(Ab + ks * 32 + 8 * ARB + 16);
        const uint2* Bk = Wt + ks * 512;
        #pragma unroll
        for (int nt = 0; nt < 8; nt++) {
            uint2 b = Bk[nt * 32];
            mma16(acc[nt], a0, a1, a2, a3, b.x, b.y);
        }
    }
}

// ---- prep: x -> fp16, weights -> fragment-major fp16 ----
__global__ void prep(const float* __restrict__ x, const float* __restrict__ W1,
                     const float* __restrict__ W2, const float* __restrict__ W3, int N) {
    int t = blockIdx.x * blockDim.x + threadIdx.x;
    int s = gridDim.x * blockDim.x;
    const float2* x2 = (const float2*)x;
    int nx = N * 64;
    for (int i = t; i < nx; i += s) { float2 v = x2[i]; g_xh[i] = f22h2(v.x, v.y); }
    for (int i = t; i < 2 * 512; i += s) {
        int lane = i & 31, nt = (i >> 5) & 7, cb = (i >> 8) & 1, ks = i >> 9;
        int n = cb * 64 + nt * 8 + (lane >> 2), k0 = ks * 16 + (lane & 3) * 2;
        g_W1h[i] = make_uint2(f22h2(W1[k0 * 128 + n], W1[(k0 + 1) * 128 + n]),
                              f22h2(W1[(k0 + 8) * 128 + n], W1[(k0 + 9) * 128 + n]));
    }
    for (int i = t; i < 24 * 512; i += s) {
        int lane = i & 31, nt = (i >> 5) & 7, cb = (i >> 8) & 1, ks = i >> 9;
        int n = cb * 64 + nt * 8 + (lane >> 2), k0 = ks * 16 + (lane & 3) * 2;
        g_W2h[i] = make_uint2(f22h2(W2[k0 * 128 + n], W2[(k0 + 1) * 128 + n]),
                              f22h2(W2[(k0 + 8) * 128 + n], W2[(k0 + 9) * 128 + n]));
    }
    for (int i = t; i < 8 * 512; i += s) {
        int lane = i & 31, nt = (i >> 5) & 7, cb = (i >> 8) & 1, ks = i >> 9;
        int n = cb * 64 + nt * 8 + (lane >> 2), k0 = ks * 16 + (lane & 3) * 2;
        g_W3h[i] = make_uint2(f22h2(W3[k0 * 128 + n], W3[(k0 + 1) * 128 + n]),
                              f22h2(W3[(k0 + 8) * 128 + n], W3[(k0 + 9) * 128 + n]));
    }
}

#define ZACC(a) { _Pragma("unroll") for (int _n = 0; _n < 8; _n++) { \
    (a)[_n][0]=0.f;(a)[_n][1]=0.f;(a)[_n][2]=0.f;(a)[_n][3]=0.f; } }

__global__ void __launch_bounds__(NT, 2)
edge_kernel(const int* __restrict__ ei, const float* __restrict__ ea,
            const float* __restrict__ b1, const float* __restrict__ b2,
            const float* __restrict__ gamma, const float* __restrict__ beta,
            const float* __restrict__ mean, const float* __restrict__ var,
            const float* __restrict__ b3,
            float* __restrict__ out, int E, int ntiles)
{
    extern __shared__ char smem[];
    const unsigned sb = smem_u32(smem);
    int*   sIdx   = (int*)(smem + OFF_IDX);
    float* sScale = (float*)(smem + OFF_SC);
    float* sShift = (float*)(smem + OFF_SC + 512);
    float* sB1    = (float*)(smem + OFF_SC + 1024);
    float* sB3    = (float*)(smem + OFF_SC + 1536);
    const float* sEAf = (const float*)(smem + OFF_EAF);

    const int tid = threadIdx.x;
    const int w = tid >> 5, lane = tid & 31;
    const int gid = lane >> 2, tig = lane & 3;
    const int rbase = (w >> 1) * 16, cb = w & 1, cbase = cb * 64;
    const int r4 = tid >> 2, q4 = tid & 3;

    if (tid < 128) {
        float sc = gamma[tid] * rsqrtf(var[tid] + 1e-5f);
        sScale[tid] = sc;
        sShift[tid] = (b2[tid] - mean[tid]) * sc + beta[tid];
        sB1[tid] = b1[tid];
        sB3[tid] = b3[tid];
    }
    const bool is64 = ((ei[1] | ei[3] | ei[5] | ei[7]) == 0);
    const long long* ei64 = (const long long*)ei;

    const int r0 = rbase + gid;
    const char* pA0 = smem + OFF_A0 + r0 * ARB + tig * 4;
    const char* pA1 = smem + OFF_A1 + r0 * ARB + tig * 4;
    char* wA0 = smem + OFF_A0;
    char* wA1 = smem + OFF_A1;
    const uint2* Wt0 = (const uint2*)(smem + OFF_WB0) + (cb << 8) + lane;
    const uint2* Wt1 = (const uint2*)(smem + OFF_WB1) + (cb << 8) + lane;
    const uint2* Wt2 = (const uint2*)(smem + OFF_WB2) + (cb << 8) + lane;

    #define LOADW16(OFF, gsrc) { const uint2* _s = (gsrc) + tid * 8; \
        unsigned _d = sb + (OFF) + tid * 64; \
        _Pragma("unroll") for (int _i = 0; _i < 4; _i++) CP16(_d + _i * 16, _s + _i * 2); \
        CP_COMMIT(); }
    #define LOADW8(OFF, gsrc) { const uint2* _s = (gsrc) + tid * 4; \
        unsigned _d = sb + (OFF) + tid * 32; \
        CP16(_d, _s); CP16(_d + 16, _s + 2); CP_COMMIT(); }
    #define LOADEA(eb) { int _ge = min((eb) + r4, E - 1); \
        const float* _s = ea + (long long)_ge * 32 + q4 * 8; \
        unsigned _d = sb + OFF_EAF + r4 * 128 + q4 * 32; \
        CP16(_d, _s); CP16(_d + 16, _s + 4); CP_COMMIT(); }
    #define LOADX(AOFF, idxp) { \
        const char* _s = (const char*)g_xh + (long long)(idxp)[r4] * 256 + q4 * 64; \
        unsigned _d = sb + (AOFF) + r4 * ARB + q4 * 64; \
        _Pragma("unroll") for (int _i = 0; _i < 4; _i++) CP16(_d + _i * 16, _s + _i * 16); \
        CP_COMMIT(); }
    #define LOADIDX(dst, eb) { \
        if (tid < 64) { int _e = min((eb) + tid, E - 1); \
            (dst)[tid] = is64 ? (int)ei64[_e] : ei[_e]; \
        } else if (tid < 128) { int _e = min((eb) + tid - 64, E - 1); \
            (dst)[64 + tid - 64 + 0] = 0; \
            (dst)[tid] = is64 ? (int)ei64[(long long)E + _e] : ei[E + _e]; } }

    // ---- preamble ----
    int pp = 0;
    const int tile0 = blockIdx.x;
    LOADIDX(sIdx, tile0 * 64);
    __syncthreads();
    LOADW8(OFF_WB0, g_W1h);                 // W1
    LOADEA(tile0 * 64);                     // EA
    LOADW16(OFF_WB1, g_W2h + 8192);         // c2a
    LOADW16(OFF_WB2, g_W2h + 10240);        // c2b
    LOADX(OFF_A1, sIdx);                    // xrow

    for (int tile = tile0; tile < ntiles; tile += gridDim.x) {
        const int ebase = tile * 64;
        int* curIdx = sIdx + pp * 128;
        int* nxtIdx = sIdx + (pp ^ 1) * 128;
        int nxt = tile + gridDim.x;
        int nebase = (nxt < ntiles ? nxt : tile) * 64;

        CP_WAIT(2);  __syncthreads();        // W1, EA, c2a in
        // EA cvt fp32 -> fp16 into A0 cols 0..31
        {
            const float* s = sEAf + r4 * 32 + q4 * 8;
            uint4 u;
            u.x = f22h2(s[0], s[1]); u.y = f22h2(s[2], s[3]);
            u.z = f22h2(s[4], s[5]); u.w = f22h2(s[6], s[7]);
            *(uint4*)(wA0 + r4 * ARB + q4 * 16) = u;
        }
        __syncthreads();

        float eacc[8][4]; ZACC(eacc);
        seg16<2>(pA0, Wt0, eacc);            // MMA1: EA @ W1
        __syncthreads();
        // epi1: tanh -> A0 fp16
        #pragma unroll
        for (int nt = 0; nt < 8; nt++) {
            int c = cbase + nt * 8 + 2 * tig;
            float blo = sB1[c], bhi = sB1[c + 1];
            *(unsigned*)(wA0 + r0 * ARB + c * 2) =
                f22h2(fast_tanh(eacc[nt][0] + blo), fast_tanh(eacc[nt][1] + bhi));
            *(unsigned*)(wA0 + (r0 + 8) * ARB + c * 2) =
                f22h2(fast_tanh(eacc[nt][2] + blo), fast_tanh(eacc[nt][3] + bhi));
        }
        LOADW16(OFF_WB0, g_W2h + 0);         // c0a
        CP_WAIT(2); __syncthreads();         // c2b in
        float hacc[8][4]; ZACC(hacc);
        seg16<4>(pA0, Wt1, hacc);            // e.lo @ c2a
        __syncthreads();
        LOADW16(OFF_WB1, g_W2h + 2048);      // c0b
        seg16<4>(pA0 + 128, Wt2, hacc);      // e.hi @ c2b
        CP_WAIT(1); __syncthreads();         // xrow + c0a in
        LOADW16(OFF_WB2, g_W2h + 4096);      // c1a
        LOADX(OFF_A0, curIdx + 64);          // xcol
        seg16<4>(pA1, Wt0, hacc);            // xrow.lo @ c0a
        CP_WAIT(2); __syncthreads();         // c0b in
        LOADW16(OFF_WB0, g_W2h + 6144);      // c1b
        seg16<4>(pA1 + 128, Wt1, hacc);      // xrow.hi @ c0b
        CP_WAIT(1); __syncthreads();         // c1a + xcol in
        LOADW16(OFF_WB1, g_W3h + 0);         // w3a
        seg16<4>(pA0, Wt2, hacc);            // xcol.lo @ c1a
        CP_WAIT(1); __syncthreads();         // c1b in
        LOADW16(OFF_WB2, g_W3h + 2048);      // w3b
        seg16<4>(pA0 + 128, Wt0, hacc);      // xcol.hi @ c1b
        __syncthreads();

        // epi2: BN + relu -> A1 fp16 ; prefetch next tile
        #pragma unroll
        for (int nt = 0; nt < 8; nt++) {
            int c = cbase + nt * 8 + 2 * tig;
            float sc0 = sScale[c], sc1 = sScale[c + 1];
            float sh0 = sShift[c], sh1 = sShift[c + 1];
            *(unsigned*)(wA1 + r0 * ARB + c * 2) = f22h2(
                fmaxf(fmaf(hacc[nt][0], sc0, sh0), 0.f),
                fmaxf(fmaf(hacc[nt][1], sc1, sh1), 0.f));
            *(unsigned*)(wA1 + (r0 + 8) * ARB + c * 2) = f22h2(
                fmaxf(fmaf(hacc[nt][2], sc0, sh0), 0.f),
                fmaxf(fmaf(hacc[nt][3], sc1, sh1), 0.f));
        }
        LOADIDX(nxtIdx, nebase);
        LOADW8(OFF_WB0, g_W1h);              // W1'
        LOADEA(nebase);                      // EA'
        CP_WAIT(3); __syncthreads();         // w3a in
        float yacc[8][4]; ZACC(yacc);
        seg16<4>(pA1, Wt1, yacc);            // h.lo @ w3a
        CP_WAIT(3); __syncthreads();         // w3b in
        LOADW16(OFF_WB1, g_W2h + 8192);      // c2a'
        seg16<4>(pA1 + 128, Wt2, yacc);      // h.hi @ w3b

        // epi3: relu(y + b3) -> gmem
        {
            int e0 = ebase + r0, e1 = e0 + 8;
            float* po0 = out + (long long)e0 * 128;
            float* po1 = out + (long long)e1 * 128;
            #pragma unroll
            for (int nt = 0; nt < 8; nt++) {
                int c = cbase + nt * 8 + 2 * tig;
                float blo = sB3[c], bhi = sB3[c + 1];
                if (e0 < E) st_cs_v2(po0 + c, fmaxf(yacc[nt][0] + blo, 0.f),
                                              fmaxf(yacc[nt][1] + bhi, 0.f));
                if (e1 < E) st_cs_v2(po1 + c, fmaxf(yacc[nt][2] + blo, 0.f),
                                              fmaxf(yacc[nt][3] + bhi, 0.f));
            }
        }
        __syncthreads();
        LOADW16(OFF_WB2, g_W2h + 10240);     // c2b'
        LOADX(OFF_A1, nxtIdx);               // xrow'
        pp ^= 1;
    }
    CP_WAIT(0);
    __syncthreads();
}

extern "C" void kernel_launch(void* const* d_in, const int* in_sizes, int n_in,
                              void* d_out, int out_size) {
    const float* x     = (const float*)d_in[0];
    const int*   ei    = (const int*)  d_in[1];
    const float* eattr = (const float*)d_in[2];
    const float* W1    = (const float*)d_in[3];
    const float* b1    = (const float*)d_in[4];
    const float* W2    = (const float*)d_in[5];
    const float* b2    = (const float*)d_in[6];
    const float* gam   = (const float*)d_in[7];
    const float* bet   = (const float*)d_in[8];
    const float* mean  = (const float*)d_in[9];
    const float* var   = (const float*)d_in[10];
    const float* W3    = (const float*)d_in[11];
    const float* b3    = (const float*)d_in[12];
    float* out = (float*)d_out;

    int N = in_sizes[0] / 128;
    int E = in_sizes[2] / 32;
    int ntiles = (E + 63) / 64;

    cudaFuncSetAttribute(edge_kernel, cudaFuncAttributeMaxDynamicSharedMemorySize, SMEM_TOTAL);

    prep<<<1024, 256>>>(x, W1, W2, W3, N);
    edge_kernel<<<296, NT, SMEM_TOTAL>>>(ei, eattr, b1, b2, gam, bet,
                                         mean, var, b3, out, E, ntiles);
}

// round 8
// speedup vs baseline: 9.0549x; 1.2937x over previous
#include <cuda_runtime.h>

#define NT 512

// ---- smem layout (bytes) ----
#define OFF_IDX  0         // 2 x (128 row + 128 col) ints = 2048
#define OFF_SC   2048      // scale,shift,b1,b3 = 2048
#define OFF_W1   4096      // 8192   (2 ksteps of frags)
#define OFF_W2   12288     // 98304  (24 ksteps)
#define OFF_W3   110592    // 32768  (8 ksteps)
#define OFF_B0   143360    // 34816  (128 rows x 136 halfs)
#define OFF_B1   178176    // 34816
#define OFF_STG  212992    // 16384  (EA fp32 staging)
#define SMEM_TOTAL 229376

#define ARB 272            // A row stride in bytes (136 halfs)

// ---- device scratch ----
__device__ __align__(16) unsigned g_xh[131072 * 64];   // x as fp16x2
__device__ __align__(16) uint2 g_W1f[2 * 512];
__device__ __align__(16) uint2 g_W2f[24 * 512];
__device__ __align__(16) uint2 g_W3f[8 * 512];

#define CP16(dst, src)  asm volatile("cp.async.cg.shared.global [%0], [%1], 16;" :: "r"(dst), "l"(src) : "memory")
#define CP_COMMIT()     asm volatile("cp.async.commit_group;" ::: "memory")
#define CP_WAIT(n)      asm volatile("cp.async.wait_group %0;" :: "n"(n) : "memory")

__device__ __forceinline__ unsigned smem_u32(const void* p) {
    unsigned a;
    asm("{ .reg .u64 t; cvta.to.shared.u64 t, %1; cvt.u32.u64 %0, t; }" : "=r"(a) : "l"(p));
    return a;
}
__device__ __forceinline__ unsigned f22h2(float lo, float hi) {
    unsigned r;
    asm("cvt.rn.f16x2.f32 %0, %1, %2;" : "=r"(r) : "f"(hi), "f"(lo));
    return r;
}
__device__ __forceinline__ void mma16(float* c, unsigned a0, unsigned a1, unsigned a2,
                                      unsigned a3, unsigned b0, unsigned b1) {
    asm volatile("mma.sync.aligned.m16n8k16.row.col.f32.f16.f16.f32 "
        "{%0,%1,%2,%3}, {%4,%5,%6,%7}, {%8,%9}, {%0,%1,%2,%3};"
        : "+f"(c[0]), "+f"(c[1]), "+f"(c[2]), "+f"(c[3])
        : "r"(a0), "r"(a1), "r"(a2), "r"(a3), "r"(b0), "r"(b1));
}
__device__ __forceinline__ float fast_tanh(float v) {
    float z, r;
    asm("ex2.approx.f32 %0, %1;" : "=f"(z) : "f"(fabsf(v) * -2.885390081777927f));
    asm("rcp.approx.f32 %0, %1;" : "=f"(r) : "f"(1.0f + z));
    return copysignf((1.0f - z) * r, v);
}
__device__ __forceinline__ void st_cs_v2(float* p, float a, float b) {
    asm volatile("st.global.cs.v2.f32 [%0], {%1,%2};" :: "l"(p), "f"(a), "f"(b) : "memory");
}

// warp GEMM segment: acc[2][4][4] += A[32 x 16*KS] * W (frag-major resident)
// Ab = Abuf + (rb+gid)*ARB + tig*4 ;  Wt = frag base + cq*128 + lane
template<int KS>
__device__ __forceinline__ void seg(const char* Ab, const uint2* Wt, float acc[2][4][4]) {
    #pragma unroll
    for (int ks = 0; ks < KS; ks++) {
        unsigned a[2][4];
        #pragma unroll
        for (int mt = 0; mt < 2; mt++) {
            const char* Am = Ab + ks * 32 + mt * 16 * ARB;
            a[mt][0] = *(const unsigned*)(Am);
            a[mt][1] = *(const unsigned*)(Am + 8 * ARB);
            a[mt][2] = *(const unsigned*)(Am + 16);
            a[mt][3] = *(const unsigned*)(Am + 8 * ARB + 16);
        }
        const uint2* Bk = Wt + ks * 512;
        #pragma unroll
        for (int nt = 0; nt < 4; nt++) {
            uint2 b = Bk[nt * 32];
            mma16(acc[0][nt], a[0][0], a[0][1], a[0][2], a[0][3], b.x, b.y);
            mma16(acc[1][nt], a[1][0], a[1][1], a[1][2], a[1][3], b.x, b.y);
        }
    }
}

#define ZACC(a) { _Pragma("unroll") for (int _m = 0; _m < 2; _m++) \
    _Pragma("unroll") for (int _n = 0; _n < 4; _n++) { \
    (a)[_m][_n][0]=0.f;(a)[_m][_n][1]=0.f;(a)[_m][_n][2]=0.f;(a)[_m][_n][3]=0.f; } }

// ---- prep: x -> fp16, weights -> fragment-major fp16 ----
__global__ void prep(const float* __restrict__ x, const float* __restrict__ W1,
                     const float* __restrict__ W2, const float* __restrict__ W3, int N) {
    int t = blockIdx.x * blockDim.x + threadIdx.x;
    int s = gridDim.x * blockDim.x;
    const float2* x2 = (const float2*)x;
    int nx = N * 64;
    for (int i = t; i < nx; i += s) { float2 v = x2[i]; g_xh[i] = f22h2(v.x, v.y); }
    for (int i = t; i < 2 * 512; i += s) {
        int lane = i & 31, nt = (i >> 5) & 3, cq = (i >> 7) & 3, ks = i >> 9;
        int n = cq * 32 + nt * 8 + (lane >> 2), k0 = ks * 16 + (lane & 3) * 2;
        g_W1f[i] = make_uint2(f22h2(W1[k0 * 128 + n], W1[(k0 + 1) * 128 + n]),
                              f22h2(W1[(k0 + 8) * 128 + n], W1[(k0 + 9) * 128 + n]));
    }
    for (int i = t; i < 24 * 512; i += s) {
        int lane = i & 31, nt = (i >> 5) & 3, cq = (i >> 7) & 3, ks = i >> 9;
        int n = cq * 32 + nt * 8 + (lane >> 2), k0 = ks * 16 + (lane & 3) * 2;
        g_W2f[i] = make_uint2(f22h2(W2[k0 * 128 + n], W2[(k0 + 1) * 128 + n]),
                              f22h2(W2[(k0 + 8) * 128 + n], W2[(k0 + 9) * 128 + n]));
    }
    for (int i = t; i < 8 * 512; i += s) {
        int lane = i & 31, nt = (i >> 5) & 3, cq = (i >> 7) & 3, ks = i >> 9;
        int n = cq * 32 + nt * 8 + (lane >> 2), k0 = ks * 16 + (lane & 3) * 2;
        g_W3f[i] = make_uint2(f22h2(W3[k0 * 128 + n], W3[(k0 + 1) * 128 + n]),
                              f22h2(W3[(k0 + 8) * 128 + n], W3[(k0 + 9) * 128 + n]));
    }
}

__global__ void __launch_bounds__(NT, 1)
edge_kernel(const int* __restrict__ ei, const float* __restrict__ ea,
            const float* __restrict__ b1, const float* __restrict__ b2,
            const float* __restrict__ gamma, const float* __restrict__ beta,
            const float* __restrict__ mean, const float* __restrict__ var,
            const float* __restrict__ b3,
            float* __restrict__ out, int E, int ntiles)
{
    extern __shared__ char smem[];
    const unsigned sb = smem_u32(smem);
    int*   sIdx   = (int*)(smem + OFF_IDX);          // [2][256]
    float* sScale = (float*)(smem + OFF_SC);
    float* sShift = (float*)(smem + OFF_SC + 512);
    float* sB1    = (float*)(smem + OFF_SC + 1024);
    float* sB3    = (float*)(smem + OFF_SC + 1536);
    char* B0 = smem + OFF_B0;
    char* B1 = smem + OFF_B1;
    const float* stg = (const float*)(smem + OFF_STG);

    const int tid = threadIdx.x;
    const int w = tid >> 5, lane = tid & 31;
    const int gid = lane >> 2, tig = lane & 3;
    const int rg = w >> 2, cq = w & 3;
    const int rb = rg * 32, cbase = cq * 32;
    const int r4 = tid >> 2, q4 = tid & 3;

    // ---- once: constants + resident weights ----
    if (tid < 128) {
        float sc = gamma[tid] * rsqrtf(var[tid] + 1e-5f);
        sScale[tid] = sc;
        sShift[tid] = (b2[tid] - mean[tid]) * sc + beta[tid];
        sB1[tid] = b1[tid];
        sB3[tid] = b3[tid];
    }
    {
        CP16(sb + OFF_W1 + tid * 16, (const char*)g_W1f + tid * 16);
        #pragma unroll
        for (int i = 0; i < 12; i++)
            CP16(sb + OFF_W2 + (i * NT + tid) * 16, (const char*)g_W2f + (i * NT + tid) * 16);
        #pragma unroll
        for (int i = 0; i < 4; i++)
            CP16(sb + OFF_W3 + (i * NT + tid) * 16, (const char*)g_W3f + (i * NT + tid) * 16);
        CP_COMMIT();
    }
    CP_WAIT(0);
    __syncthreads();

    const bool is64 = ((ei[1] | ei[3] | ei[5] | ei[7]) == 0);
    const long long* ei64 = (const long long*)ei;

    const char* A0th = B0 + (rb + gid) * ARB + tig * 4;
    const char* A1th = B1 + (rb + gid) * ARB + tig * 4;
    const uint2* W1t = (const uint2*)(smem + OFF_W1) + cq * 128 + lane;
    const uint2* W2t = (const uint2*)(smem + OFF_W2) + cq * 128 + lane;
    const uint2* W3t = (const uint2*)(smem + OFF_W3) + cq * 128 + lane;

    #define LOADIDX(slot, eb) { \
        if (tid < 128) { int _e = min((eb) + tid, E - 1); \
            sIdx[(slot) * 256 + tid] = is64 ? (int)ei64[_e] : ei[_e]; \
        } else if (tid < 256) { int _e = min((eb) + tid - 128, E - 1); \
            sIdx[(slot) * 256 + tid] = is64 ? (int)ei64[(long long)E + _e] : ei[E + _e]; } }
    #define LOADEA(eb) { int _ge = min((eb) + r4, E - 1); \
        const float* _s = ea + (long long)_ge * 32 + q4 * 8; \
        unsigned _d = sb + OFF_STG + r4 * 128 + q4 * 32; \
        CP16(_d, _s); CP16(_d + 16, _s + 4); CP_COMMIT(); }
    #define LOADX(BUF, idxp) { \
        const char* _s = (const char*)g_xh + (long long)(idxp)[r4] * 256 + q4 * 64; \
        unsigned _d = sb + (BUF) + r4 * ARB + q4 * 64; \
        CP16(_d, _s); CP16(_d + 16, _s + 16); \
        CP16(_d + 32, _s + 32); CP16(_d + 48, _s + 48); CP_COMMIT(); }

    // ---- preamble: idx(t0), EA(t0), xrow(t0) ----
    int pp = 0;
    const int tile0 = blockIdx.x;
    LOADIDX(0, tile0 * 128);
    __syncthreads();
    LOADEA(tile0 * 128);            // G: EA(t0) -> staging
    LOADX(OFF_B0, sIdx);            // G: xrow(t0) -> B0

    float acc[2][4][4];

    for (int tile = tile0; tile < ntiles; tile += gridDim.x) {
        const int ebase = tile * 128;
        const int* curIdx = sIdx + pp * 256;
        const int* nxtIdx = sIdx + (pp ^ 1) * 256;
        int nxt = tile + gridDim.x;
        int nebase = (nxt < ntiles ? nxt : tile) * 128;

        // 1. EA staged -> cvt into B1 cols 0..31
        CP_WAIT(1); __syncthreads();
        {
            const float* s = stg + r4 * 32 + q4 * 8;
            uint4 u;
            u.x = f22h2(s[0], s[1]); u.y = f22h2(s[2], s[3]);
            u.z = f22h2(s[4], s[5]); u.w = f22h2(s[6], s[7]);
            *(uint4*)(B1 + r4 * ARB + q4 * 16) = u;
        }
        __syncthreads();

        // 2. MMA1: e = EA @ W1
        ZACC(acc);
        seg<2>(A1th, W1t, acc);
        __syncthreads();

        // 3. epi1: tanh -> B1 (full 128 cols, fp16)
        #pragma unroll
        for (int mt = 0; mt < 2; mt++) {
            int r = rb + mt * 16 + gid;
            #pragma unroll
            for (int nt = 0; nt < 4; nt++) {
                int c = cbase + nt * 8 + tig * 2;
                float blo = sB1[c], bhi = sB1[c + 1];
                *(unsigned*)(B1 + r * ARB + c * 2) =
                    f22h2(fast_tanh(acc[mt][nt][0] + blo), fast_tanh(acc[mt][nt][1] + bhi));
                *(unsigned*)(B1 + (r + 8) * ARB + c * 2) =
                    f22h2(fast_tanh(acc[mt][nt][2] + blo), fast_tanh(acc[mt][nt][3] + bhi));
            }
        }
        __syncthreads();

        // 4. MMA2a: h = e @ W2c2 (ksteps 16..23)
        ZACC(acc);
        seg<8>(A1th, W2t + 16 * 512, acc);
        __syncthreads();

        // 5. issue xcol(t) -> B1 (e consumed)
        LOADX(OFF_B1, curIdx + 128);

        // 6. MMA2b: h += xrow @ W2c0
        CP_WAIT(1); __syncthreads();
        seg<8>(A0th, W2t, acc);

        // 7. MMA2c: h += xcol @ W2c1
        CP_WAIT(0); __syncthreads();
        seg<8>(A1th, W2t + 8 * 512, acc);
        __syncthreads();

        // 8. issue EA(t+1) -> staging (B1 consumed, staging free)
        LOADEA(nebase);

        // 9. epi2: h = relu(BN) -> B0 (xrow consumed) ; load idx(t+1)
        #pragma unroll
        for (int mt = 0; mt < 2; mt++) {
            int r = rb + mt * 16 + gid;
            #pragma unroll
            for (int nt = 0; nt < 4; nt++) {
                int c = cbase + nt * 8 + tig * 2;
                float sc0 = sScale[c], sc1 = sScale[c + 1];
                float sh0 = sShift[c], sh1 = sShift[c + 1];
                *(unsigned*)(B0 + r * ARB + c * 2) = f22h2(
                    fmaxf(fmaf(acc[mt][nt][0], sc0, sh0), 0.f),
                    fmaxf(fmaf(acc[mt][nt][1], sc1, sh1), 0.f));
                *(unsigned*)(B0 + (r + 8) * ARB + c * 2) = f22h2(
                    fmaxf(fmaf(acc[mt][nt][2], sc0, sh0), 0.f),
                    fmaxf(fmaf(acc[mt][nt][3], sc1, sh1), 0.f));
            }
        }
        LOADIDX(pp ^ 1, nebase);
        __syncthreads();

        // 10. MMA3: y = h @ W3
        ZACC(acc);
        seg<8>(A0th, W3t, acc);
        __syncthreads();

        // 11. issue xrow(t+1) -> B0 (h consumed)
        LOADX(OFF_B0, nxtIdx);

        // 12. epi3: relu(y + b3) -> gmem
        #pragma unroll
        for (int mt = 0; mt < 2; mt++) {
            int r = rb + mt * 16 + gid;
            int e0 = ebase + r, e1 = e0 + 8;
            float* po0 = out + (long long)e0 * 128;
            float* po1 = out + (long long)e1 * 128;
            #pragma unroll
            for (int nt = 0; nt < 4; nt++) {
                int c = cbase + nt * 8 + tig * 2;
                float blo = sB3[c], bhi = sB3[c + 1];
                if (e0 < E) st_cs_v2(po0 + c, fmaxf(acc[mt][nt][0] + blo, 0.f),
                                              fmaxf(acc[mt][nt][1] + bhi, 0.f));
                if (e1 < E) st_cs_v2(po1 + c, fmaxf(acc[mt][nt][2] + blo, 0.f),
                                              fmaxf(acc[mt][nt][3] + bhi, 0.f));
            }
        }
        pp ^= 1;
    }
    CP_WAIT(0);
    __syncthreads();
}

extern "C" void kernel_launch(void* const* d_in, const int* in_sizes, int n_in,
                              void* d_out, int out_size) {
    const float* x     = (const float*)d_in[0];
    const int*   ei    = (const int*)  d_in[1];
    const float* eattr = (const float*)d_in[2];
    const float* W1    = (const float*)d_in[3];
    const float* b1    = (const float*)d_in[4];
    const float* W2    = (const float*)d_in[5];
    const float* b2    = (const float*)d_in[6];
    const float* gam   = (const float*)d_in[7];
    const float* bet   = (const float*)d_in[8];
    const float* mean  = (const float*)d_in[9];
    const float* var   = (const float*)d_in[10];
    const float* W3    = (const float*)d_in[11];
    const float* b3    = (const float*)d_in[12];
    float* out = (float*)d_out;

    int N = in_sizes[0] / 128;
    int E = in_sizes[2] / 32;
    int ntiles = (E + 127) / 128;

    cudaFuncSetAttribute(edge_kernel, cudaFuncAttributeMaxDynamicSharedMemorySize, SMEM_TOTAL);

    prep<<<1024, 256>>>(x, W1, W2, W3, N);
    edge_kernel<<<148, NT, SMEM_TOTAL>>>(ei, eattr, b1, b2, gam, bet,
                                         mean, var, b3, out, E, ntiles);
}

// round 9
// speedup vs baseline: 9.1231x; 1.0075x over previous
#include <cuda_runtime.h>
#include <cuda_fp16.h>

#define NT 512
#define ARB 272            // A row stride in bytes (136 halfs)

// ---- edge-kernel smem layout (bytes) ----
#define OFF_IDX  0         // 2 x (128 row + 128 col) ints
#define OFF_SC   2048
#define OFF_STG  4096      // EA fp32 staging 16384
#define OFF_W1   20480     // 8192
#define OFF_W2   28672     // 32768 (W2 chunk2 frags)
#define OFF_W3   61440     // 32768
#define OFF_B0   94208     // 34816
#define OFF_B1   129024    // 34816
#define SMEM_E   163840

// ---- node-kernel smem layout ----
#define NOFF_A   0         // 34816
#define NOFF_W   34816     // 65536 (W2 chunk0+1 frags)
#define SMEM_N   100352

// ---- device scratch ----
__device__ __align__(16) unsigned g_xh[131072 * 64];    // x as fp16x2
__device__ __align__(16) unsigned g_P[131072 * 128];    // projections fp16x2: [node][c0 pairs 0..63 | c1 pairs 64..127]
__device__ __align__(16) uint2 g_W1f[2 * 512];
__device__ __align__(16) uint2 g_W2f[24 * 512];
__device__ __align__(16) uint2 g_W3f[8 * 512];

#define CP16(dst, src)  asm volatile("cp.async.cg.shared.global [%0], [%1], 16;" :: "r"(dst), "l"(src) : "memory")
#define CP_COMMIT()     asm volatile("cp.async.commit_group;" ::: "memory")
#define CP_WAIT(n)      asm volatile("cp.async.wait_group %0;" :: "n"(n) : "memory")

__device__ __forceinline__ unsigned smem_u32(const void* p) {
    unsigned a;
    asm("{ .reg .u64 t; cvta.to.shared.u64 t, %1; cvt.u32.u64 %0, t; }" : "=r"(a) : "l"(p));
    return a;
}
__device__ __forceinline__ unsigned f22h2(float lo, float hi) {
    unsigned r;
    asm("cvt.rn.f16x2.f32 %0, %1, %2;" : "=r"(r) : "f"(hi), "f"(lo));
    return r;
}
__device__ __forceinline__ float2 h2f2(unsigned u) {
    __half2 h; *(unsigned*)&h = u;
    return __half22float2(h);
}
__device__ __forceinline__ void mma16(float* c, unsigned a0, unsigned a1, unsigned a2,
                                      unsigned a3, unsigned b0, unsigned b1) {
    asm volatile("mma.sync.aligned.m16n8k16.row.col.f32.f16.f16.f32 "
        "{%0,%1,%2,%3}, {%4,%5,%6,%7}, {%8,%9}, {%0,%1,%2,%3};"
        : "+f"(c[0]), "+f"(c[1]), "+f"(c[2]), "+f"(c[3])
        : "r"(a0), "r"(a1), "r"(a2), "r"(a3), "r"(b0), "r"(b1));
}
__device__ __forceinline__ float fast_tanh(float v) {
    float z, r;
    asm("ex2.approx.f32 %0, %1;" : "=f"(z) : "f"(fabsf(v) * -2.885390081777927f));
    asm("rcp.approx.f32 %0, %1;" : "=f"(r) : "f"(1.0f + z));
    return copysignf((1.0f - z) * r, v);
}
__device__ __forceinline__ void st_cs_v2(float* p, float a, float b) {
    asm volatile("st.global.cs.v2.f32 [%0], {%1,%2};" :: "l"(p), "f"(a), "f"(b) : "memory");
}

// warp GEMM segment: acc[2][4][4] += A[32 x 16*KS] * W (frag-major)
template<int KS>
__device__ __forceinline__ void seg(const char* Ab, const uint2* Wt, float acc[2][4][4]) {
    #pragma unroll
    for (int ks = 0; ks < KS; ks++) {
        unsigned a[2][4];
        #pragma unroll
        for (int mt = 0; mt < 2; mt++) {
            const char* Am = Ab + ks * 32 + mt * 16 * ARB;
            a[mt][0] = *(const unsigned*)(Am);
            a[mt][1] = *(const unsigned*)(Am + 8 * ARB);
            a[mt][2] = *(const unsigned*)(Am + 16);
            a[mt][3] = *(const unsigned*)(Am + 8 * ARB + 16);
        }
        const uint2* Bk = Wt + ks * 512;
        #pragma unroll
        for (int nt = 0; nt < 4; nt++) {
            uint2 b = Bk[nt * 32];
            mma16(acc[0][nt], a[0][0], a[0][1], a[0][2], a[0][3], b.x, b.y);
            mma16(acc[1][nt], a[1][0], a[1][1], a[1][2], a[1][3], b.x, b.y);
        }
    }
}

#define ZACC(a) { _Pragma("unroll") for (int _m = 0; _m < 2; _m++) \
    _Pragma("unroll") for (int _n = 0; _n < 4; _n++) { \
    (a)[_m][_n][0]=0.f;(a)[_m][_n][1]=0.f;(a)[_m][_n][2]=0.f;(a)[_m][_n][3]=0.f; } }

// ---- prep: x -> fp16, weights -> fragment-major fp16 ----
__global__ void prep(const float* __restrict__ x, const float* __restrict__ W1,
                     const float* __restrict__ W2, const float* __restrict__ W3, int N) {
    int t = blockIdx.x * blockDim.x + threadIdx.x;
    int s = gridDim.x * blockDim.x;
    const float2* x2 = (const float2*)x;
    int nx = N * 64;
    for (int i = t; i < nx; i += s) { float2 v = x2[i]; g_xh[i] = f22h2(v.x, v.y); }
    for (int i = t; i < 2 * 512; i += s) {
        int lane = i & 31, nt = (i >> 5) & 3, cq = (i >> 7) & 3, ks = i >> 9;
        int n = cq * 32 + nt * 8 + (lane >> 2), k0 = ks * 16 + (lane & 3) * 2;
        g_W1f[i] = make_uint2(f22h2(W1[k0 * 128 + n], W1[(k0 + 1) * 128 + n]),
                              f22h2(W1[(k0 + 8) * 128 + n], W1[(k0 + 9) * 128 + n]));
    }
    for (int i = t; i < 24 * 512; i += s) {
        int lane = i & 31, nt = (i >> 5) & 3, cq = (i >> 7) & 3, ks = i >> 9;
        int n = cq * 32 + nt * 8 + (lane >> 2), k0 = ks * 16 + (lane & 3) * 2;
        g_W2f[i] = make_uint2(f22h2(W2[k0 * 128 + n], W2[(k0 + 1) * 128 + n]),
                              f22h2(W2[(k0 + 8) * 128 + n], W2[(k0 + 9) * 128 + n]));
    }
    for (int i = t; i < 8 * 512; i += s) {
        int lane = i & 31, nt = (i >> 5) & 3, cq = (i >> 7) & 3, ks = i >> 9;
        int n = cq * 32 + nt * 8 + (lane >> 2), k0 = ks * 16 + (lane & 3) * 2;
        g_W3f[i] = make_uint2(f22h2(W3[k0 * 128 + n], W3[(k0 + 1) * 128 + n]),
                              f22h2(W3[(k0 + 8) * 128 + n], W3[(k0 + 9) * 128 + n]));
    }
}

// ---- node projections: P[n] = x[n] @ [W2c0 | W2c1]  (fp16 out) ----
__global__ void __launch_bounds__(NT, 1)
node_proj(int N) {
    extern __shared__ char smem[];
    const unsigned sb = smem_u32(smem);
    const int tid = threadIdx.x;
    const int w = tid >> 5, lane = tid & 31;
    const int gid = lane >> 2, tig = lane & 3;
    const int rb = (w >> 2) * 32, cq = w & 3, cbase = cq * 32;
    const int r4 = tid >> 2, q4 = tid & 3;

    // W2 chunk0+1 frags (ksteps 0..15) resident
    #pragma unroll
    for (int i = 0; i < 8; i++)
        CP16(sb + NOFF_W + (i * NT + tid) * 16, (const char*)g_W2f + (i * NT + tid) * 16);
    // x tile (fp16) -> A
    {
        int node = min(blockIdx.x * 128 + r4, N - 1);
        const char* s = (const char*)g_xh + (long long)node * 256 + q4 * 64;
        unsigned d = sb + NOFF_A + r4 * ARB + q4 * 64;
        CP16(d, s); CP16(d + 16, s + 16); CP16(d + 32, s + 32); CP16(d + 48, s + 48);
    }
    CP_COMMIT(); CP_WAIT(0);
    __syncthreads();

    const char* Ath = smem + NOFF_A + (rb + gid) * ARB + tig * 4;
    const uint2* Wt = (const uint2*)(smem + NOFF_W) + cq * 128 + lane;

    float acc[2][4][4];
    #pragma unroll
    for (int ch = 0; ch < 2; ch++) {
        ZACC(acc);
        seg<8>(Ath, Wt + ch * 8 * 512, acc);
        #pragma unroll
        for (int mt = 0; mt < 2; mt++) {
            int node0 = blockIdx.x * 128 + rb + mt * 16 + gid;
            int pcol = ch * 64 + (cbase >> 1) + tig;
            #pragma unroll
            for (int nt = 0; nt < 4; nt++) {
                if (node0 < N)
                    g_P[(long long)node0 * 128 + pcol + nt * 4] =
                        f22h2(acc[mt][nt][0], acc[mt][nt][1]);
                if (node0 + 8 < N)
                    g_P[(long long)(node0 + 8) * 128 + pcol + nt * 4] =
                        f22h2(acc[mt][nt][2], acc[mt][nt][3]);
            }
        }
    }
}

// ---- edge kernel ----
__global__ void __launch_bounds__(NT, 1)
edge_kernel(const int* __restrict__ ei, const float* __restrict__ ea,
            const float* __restrict__ b1, const float* __restrict__ b2,
            const float* __restrict__ gamma, const float* __restrict__ beta,
            const float* __restrict__ mean, const float* __restrict__ var,
            const float* __restrict__ b3,
            float* __restrict__ out, int E, int ntiles)
{
    extern __shared__ char smem[];
    const unsigned sb = smem_u32(smem);
    int*   sIdx   = (int*)(smem + OFF_IDX);
    float* sScale = (float*)(smem + OFF_SC);
    float* sShift = (float*)(smem + OFF_SC + 512);
    float* sB1    = (float*)(smem + OFF_SC + 1024);
    float* sB3    = (float*)(smem + OFF_SC + 1536);
    const float* stg = (const float*)(smem + OFF_STG);
    char* B0 = smem + OFF_B0;
    char* B1 = smem + OFF_B1;
    const unsigned* __restrict__ gP = g_P;

    const int tid = threadIdx.x;
    const int w = tid >> 5, lane = tid & 31;
    const int gid = lane >> 2, tig = lane & 3;
    const int rb = (w >> 2) * 32, cq = w & 3, cbase = cq * 32;
    const int r4 = tid >> 2, q4 = tid & 3;

    if (tid < 128) {
        float sc = gamma[tid] * rsqrtf(var[tid] + 1e-5f);
        sScale[tid] = sc;
        sShift[tid] = (b2[tid] - mean[tid]) * sc + beta[tid];
        sB1[tid] = b1[tid];
        sB3[tid] = b3[tid];
    }
    // resident weights: W1 + W2c2 + W3
    {
        CP16(sb + OFF_W1 + tid * 16, (const char*)g_W1f + tid * 16);
        #pragma unroll
        for (int i = 0; i < 4; i++)
            CP16(sb + OFF_W2 + (i * NT + tid) * 16,
                 (const char*)(g_W2f + 16 * 512) + (i * NT + tid) * 16);
        #pragma unroll
        for (int i = 0; i < 4; i++)
            CP16(sb + OFF_W3 + (i * NT + tid) * 16, (const char*)g_W3f + (i * NT + tid) * 16);
        CP_COMMIT();
    }
    CP_WAIT(0);
    __syncthreads();

    const bool is64 = ((ei[1] | ei[3] | ei[5] | ei[7]) == 0);
    const long long* ei64 = (const long long*)ei;

    const char* A0th = B0 + (rb + gid) * ARB + tig * 4;
    const char* A1th = B1 + (rb + gid) * ARB + tig * 4;
    const uint2* W1t = (const uint2*)(smem + OFF_W1) + cq * 128 + lane;
    const uint2* W2t = (const uint2*)(smem + OFF_W2) + cq * 128 + lane;
    const uint2* W3t = (const uint2*)(smem + OFF_W3) + cq * 128 + lane;

    #define LOADIDX(slot, eb) { \
        if (tid < 128) { int _e = min((eb) + tid, E - 1); \
            sIdx[(slot) * 256 + tid] = is64 ? (int)ei64[_e] : ei[_e]; \
        } else if (tid < 256) { int _e = min((eb) + tid - 128, E - 1); \
            sIdx[(slot) * 256 + tid] = is64 ? (int)ei64[(long long)E + _e] : ei[E + _e]; } }
    #define LOADEA(eb) { int _ge = min((eb) + r4, E - 1); \
        const float* _s = ea + (long long)_ge * 32 + q4 * 8; \
        unsigned _d = sb + OFF_STG + r4 * 128 + q4 * 32; \
        CP16(_d, _s); CP16(_d + 16, _s + 4); CP_COMMIT(); }

    int pp = 0;
    const int tile0 = blockIdx.x;
    LOADIDX(0, tile0 * 128);
    __syncthreads();
    LOADEA(tile0 * 128);

    float acc[2][4][4];

    for (int tile = tile0; tile < ntiles; tile += gridDim.x) {
        const int ebase = tile * 128;
        const int* curIdx = sIdx + pp * 256;
        int nxt = tile + gridDim.x;
        int nebase = (nxt < ntiles ? nxt : tile) * 128;

        // proj prefetch into regs (consumed at epi2, ~2 MMA segments later)
        unsigned pr[16], pc[16];
        {
            int pcol = (cbase >> 1) + tig;
            #pragma unroll
            for (int mt = 0; mt < 2; mt++)
                #pragma unroll
                for (int rr = 0; rr < 2; rr++) {
                    int le = rb + mt * 16 + rr * 8 + gid;
                    long long nr = curIdx[le], nc = curIdx[128 + le];
                    #pragma unroll
                    for (int nt = 0; nt < 4; nt++) {
                        int i = mt * 8 + rr * 4 + nt;
                        pr[i] = gP[nr * 128 + pcol + nt * 4];
                        pc[i] = gP[nc * 128 + 64 + pcol + nt * 4];
                    }
                }
        }

        // 1. EA staged -> cvt fp16 into B1 cols 0..31
        CP_WAIT(0); __syncthreads();
        {
            const float* s = stg + r4 * 32 + q4 * 8;
            uint4 u;
            u.x = f22h2(s[0], s[1]); u.y = f22h2(s[2], s[3]);
            u.z = f22h2(s[4], s[5]); u.w = f22h2(s[6], s[7]);
            *(uint4*)(B1 + r4 * ARB + q4 * 16) = u;
        }
        __syncthreads();

        // 2. MMA1: e = EA @ W1
        ZACC(acc);
        seg<2>(A1th, W1t, acc);
        __syncthreads();

        // 3. epi1: tanh -> B1
        #pragma unroll
        for (int mt = 0; mt < 2; mt++) {
            int r = rb + mt * 16 + gid;
            #pragma unroll
            for (int nt = 0; nt < 4; nt++) {
                int c = cbase + nt * 8 + tig * 2;
                float blo = sB1[c], bhi = sB1[c + 1];
                *(unsigned*)(B1 + r * ARB + c * 2) =
                    f22h2(fast_tanh(acc[mt][nt][0] + blo), fast_tanh(acc[mt][nt][1] + bhi));
                *(unsigned*)(B1 + (r + 8) * ARB + c * 2) =
                    f22h2(fast_tanh(acc[mt][nt][2] + blo), fast_tanh(acc[mt][nt][3] + bhi));
            }
        }
        __syncthreads();

        // 4. MMA2: e @ W2c2
        ZACC(acc);
        seg<8>(A1th, W2t, acc);
        __syncthreads();                    // B1 + stg free

        // 5. prefetch next tile inputs
        LOADEA(nebase);
        LOADIDX(pp ^ 1, nebase);

        // 6. epi2: h = relu((acc + xr_proj + xc_proj)*scale + shift) -> B0
        #pragma unroll
        for (int mt = 0; mt < 2; mt++) {
            int r = rb + mt * 16 + gid;
            #pragma unroll
            for (int nt = 0; nt < 4; nt++) {
                int c = cbase + nt * 8 + tig * 2;
                float sc0 = sScale[c], sc1 = sScale[c + 1];
                float sh0 = sShift[c], sh1 = sShift[c + 1];
                float2 r0 = h2f2(pr[mt * 8 + nt]),     c0 = h2f2(pc[mt * 8 + nt]);
                float2 r1 = h2f2(pr[mt * 8 + 4 + nt]), c1 = h2f2(pc[mt * 8 + 4 + nt]);
                *(unsigned*)(B0 + r * ARB + c * 2) = f22h2(
                    fmaxf(fmaf(acc[mt][nt][0] + r0.x + c0.x, sc0, sh0), 0.f),
                    fmaxf(fmaf(acc[mt][nt][1] + r0.y + c0.y, sc1, sh1), 0.f));
                *(unsigned*)(B0 + (r + 8) * ARB + c * 2) = f22h2(
                    fmaxf(fmaf(acc[mt][nt][2] + r1.x + c1.x, sc0, sh0), 0.f),
                    fmaxf(fmaf(acc[mt][nt][3] + r1.y + c1.y, sc1, sh1), 0.f));
            }
        }
        __syncthreads();

        // 7. MMA3: y = h @ W3
        ZACC(acc);
        seg<8>(A0th, W3t, acc);

        // 8. epi3: relu(y + b3) -> gmem
        #pragma unroll
        for (int mt = 0; mt < 2; mt++) {
            int r = rb + mt * 16 + gid;
            int e0 = ebase + r, e1 = e0 + 8;
            float* po0 = out + (long long)e0 * 128;
            float* po1 = out + (long long)e1 * 128;
            #pragma unroll
            for (int nt = 0; nt < 4; nt++) {
                int c = cbase + nt * 8 + tig * 2;
                float blo = sB3[c], bhi = sB3[c + 1];
                if (e0 < E) st_cs_v2(po0 + c, fmaxf(acc[mt][nt][0] + blo, 0.f),
                                              fmaxf(acc[mt][nt][1] + bhi, 0.f));
                if (e1 < E) st_cs_v2(po1 + c, fmaxf(acc[mt][nt][2] + blo, 0.f),
                                              fmaxf(acc[mt][nt][3] + bhi, 0.f));
            }
        }
        pp ^= 1;
    }
    CP_WAIT(0);
    __syncthreads();
}

extern "C" void kernel_launch(void* const* d_in, const int* in_sizes, int n_in,
                              void* d_out, int out_size) {
    const float* x     = (const float*)d_in[0];
    const int*   ei    = (const int*)  d_in[1];
    const float* eattr = (const float*)d_in[2];
    const float* W1    = (const float*)d_in[3];
    const float* b1    = (const float*)d_in[4];
    const float* W2    = (const float*)d_in[5];
    const float* b2    = (const float*)d_in[6];
    const float* gam   = (const float*)d_in[7];
    const float* bet   = (const float*)d_in[8];
    const float* mean  = (const float*)d_in[9];
    const float* var   = (const float*)d_in[10];
    const float* W3    = (const float*)d_in[11];
    const float* b3    = (const float*)d_in[12];
    float* out = (float*)d_out;

    int N = in_sizes[0] / 128;
    int E = in_sizes[2] / 32;
    int ntiles = (E + 127) / 128;
    int nblocks = (N + 127) / 128;

    cudaFuncSetAttribute(node_proj, cudaFuncAttributeMaxDynamicSharedMemorySize, SMEM_N);
    cudaFuncSetAttribute(edge_kernel, cudaFuncAttributeMaxDynamicSharedMemorySize, SMEM_E);

    prep<<<1024, 256>>>(x, W1, W2, W3, N);
    node_proj<<<nblocks, NT, SMEM_N>>>(N);
    edge_kernel<<<148, NT, SMEM_E>>>(ei, eattr, b1, b2, gam, bet,
                                     mean, var, b3, out, E, ntiles);
}

// round 10
// speedup vs baseline: 9.5315x; 1.0448x over previous
#include <cuda_runtime.h>
#include <cuda_fp16.h>

#define NT 256
#define ARB 272            // A row stride in bytes (136 halfs)

// ---- edge-kernel smem layout (bytes) ----
#define OFF_IDX  0         // 2 slots x 128 ints = 1024
#define OFF_SC   1024      // scale,shift,b1,b3 = 2048
#define OFF_W1   3072      // 8192
#define OFF_W2   11264     // 32768 (W2 chunk2 frags)
#define OFF_W3   44032     // 32768
#define OFF_B0   76800     // 17408 (64 rows x 136 halfs)
#define OFF_B1   94208     // 17408
#define SMEM_E   111616

// ---- node-kernel smem layout ----
#define NOFF_A   0         // 34816 (128 rows)
#define NOFF_W   34816     // 65536
#define SMEM_N   100352

// ---- device scratch ----
__device__ __align__(16) unsigned g_xh[131072 * 64];    // x as fp16x2
__device__ __align__(16) unsigned g_P[131072 * 128];    // P[n] = x[n]@[W2c0|W2c1], fp16x2
__device__ __align__(16) uint2 g_W1f[2 * 512];
__device__ __align__(16) uint2 g_W2f[24 * 512];
__device__ __align__(16) uint2 g_W3f[8 * 512];

#define CP16(dst, src)  asm volatile("cp.async.cg.shared.global [%0], [%1], 16;" :: "r"(dst), "l"(src) : "memory")
#define CP_COMMIT()     asm volatile("cp.async.commit_group;" ::: "memory")
#define CP_WAIT(n)      asm volatile("cp.async.wait_group %0;" :: "n"(n) : "memory")

__device__ __forceinline__ unsigned smem_u32(const void* p) {
    unsigned a;
    asm("{ .reg .u64 t; cvta.to.shared.u64 t, %1; cvt.u32.u64 %0, t; }" : "=r"(a) : "l"(p));
    return a;
}
__device__ __forceinline__ unsigned f22h2(float lo, float hi) {
    unsigned r;
    asm("cvt.rn.f16x2.f32 %0, %1, %2;" : "=r"(r) : "f"(hi), "f"(lo));
    return r;
}
__device__ __forceinline__ float2 h2f2(unsigned u) {
    __half2 h; *(unsigned*)&h = u;
    return __half22float2(h);
}
__device__ __forceinline__ void mma16(float* c, unsigned a0, unsigned a1, unsigned a2,
                                      unsigned a3, unsigned b0, unsigned b1) {
    asm volatile("mma.sync.aligned.m16n8k16.row.col.f32.f16.f16.f32 "
        "{%0,%1,%2,%3}, {%4,%5,%6,%7}, {%8,%9}, {%0,%1,%2,%3};"
        : "+f"(c[0]), "+f"(c[1]), "+f"(c[2]), "+f"(c[3])
        : "r"(a0), "r"(a1), "r"(a2), "r"(a3), "r"(b0), "r"(b1));
}
__device__ __forceinline__ float fast_tanh(float v) {
    float z, r;
    asm("ex2.approx.f32 %0, %1;" : "=f"(z) : "f"(fabsf(v) * -2.885390081777927f));
    asm("rcp.approx.f32 %0, %1;" : "=f"(r) : "f"(1.0f + z));
    return copysignf((1.0f - z) * r, v);
}
__device__ __forceinline__ void st_cs_v2(float* p, float a, float b) {
    asm volatile("st.global.cs.v2.f32 [%0], {%1,%2};" :: "l"(p), "f"(a), "f"(b) : "memory");
}

// warp GEMM segment: acc[2][4][4] += A[32 x 16*KS] * W (frag-major)
template<int KS>
__device__ __forceinline__ void seg(const char* Ab, const uint2* Wt, float acc[2][4][4]) {
    #pragma unroll
    for (int ks = 0; ks < KS; ks++) {
        unsigned a[2][4];
        #pragma unroll
        for (int mt = 0; mt < 2; mt++) {
            const char* Am = Ab + ks * 32 + mt * 16 * ARB;
            a[mt][0] = *(const unsigned*)(Am);
            a[mt][1] = *(const unsigned*)(Am + 8 * ARB);
            a[mt][2] = *(const unsigned*)(Am + 16);
            a[mt][3] = *(const unsigned*)(Am + 8 * ARB + 16);
        }
        const uint2* Bk = Wt + ks * 512;
        #pragma unroll
        for (int nt = 0; nt < 4; nt++) {
            uint2 b = Bk[nt * 32];
            mma16(acc[0][nt], a[0][0], a[0][1], a[0][2], a[0][3], b.x, b.y);
            mma16(acc[1][nt], a[1][0], a[1][1], a[1][2], a[1][3], b.x, b.y);
        }
    }
}

#define ZACC(a) { _Pragma("unroll") for (int _m = 0; _m < 2; _m++) \
    _Pragma("unroll") for (int _n = 0; _n < 4; _n++) { \
    (a)[_m][_n][0]=0.f;(a)[_m][_n][1]=0.f;(a)[_m][_n][2]=0.f;(a)[_m][_n][3]=0.f; } }

// ---- prep: x -> fp16, weights -> fragment-major fp16 ----
__global__ void prep(const float* __restrict__ x, const float* __restrict__ W1,
                     const float* __restrict__ W2, const float* __restrict__ W3, int N) {
    int t = blockIdx.x * blockDim.x + threadIdx.x;
    int s = gridDim.x * blockDim.x;
    const float2* x2 = (const float2*)x;
    int nx = N * 64;
    for (int i = t; i < nx; i += s) { float2 v = x2[i]; g_xh[i] = f22h2(v.x, v.y); }
    for (int i = t; i < 2 * 512; i += s) {
        int lane = i & 31, nt = (i >> 5) & 3, cq = (i >> 7) & 3, ks = i >> 9;
        int n = cq * 32 + nt * 8 + (lane >> 2), k0 = ks * 16 + (lane & 3) * 2;
        g_W1f[i] = make_uint2(f22h2(W1[k0 * 128 + n], W1[(k0 + 1) * 128 + n]),
                              f22h2(W1[(k0 + 8) * 128 + n], W1[(k0 + 9) * 128 + n]));
    }
    for (int i = t; i < 24 * 512; i += s) {
        int lane = i & 31, nt = (i >> 5) & 3, cq = (i >> 7) & 3, ks = i >> 9;
        int n = cq * 32 + nt * 8 + (lane >> 2), k0 = ks * 16 + (lane & 3) * 2;
        g_W2f[i] = make_uint2(f22h2(W2[k0 * 128 + n], W2[(k0 + 1) * 128 + n]),
                              f22h2(W2[(k0 + 8) * 128 + n], W2[(k0 + 9) * 128 + n]));
    }
    for (int i = t; i < 8 * 512; i += s) {
        int lane = i & 31, nt = (i >> 5) & 3, cq = (i >> 7) & 3, ks = i >> 9;
        int n = cq * 32 + nt * 8 + (lane >> 2), k0 = ks * 16 + (lane & 3) * 2;
        g_W3f[i] = make_uint2(f22h2(W3[k0 * 128 + n], W3[(k0 + 1) * 128 + n]),
                              f22h2(W3[(k0 + 8) * 128 + n], W3[(k0 + 9) * 128 + n]));
    }
}

// ---- node projections: P[n] = x[n] @ [W2c0 | W2c1] (512 threads) ----
__global__ void __launch_bounds__(512, 1)
node_proj(int N) {
    extern __shared__ char smem[];
    const unsigned sb = smem_u32(smem);
    const int tid = threadIdx.x;
    const int w = tid >> 5, lane = tid & 31;
    const int gid = lane >> 2, tig = lane & 3;
    const int rb = (w >> 2) * 32, cq = w & 3, cbase = cq * 32;
    const int r4 = tid >> 2, q4 = tid & 3;

    #pragma unroll
    for (int i = 0; i < 8; i++)
        CP16(sb + NOFF_W + (i * 512 + tid) * 16, (const char*)g_W2f + (i * 512 + tid) * 16);
    {
        int node = min(blockIdx.x * 128 + r4, N - 1);
        const char* s = (const char*)g_xh + (long long)node * 256 + q4 * 64;
        unsigned d = sb + NOFF_A + r4 * ARB + q4 * 64;
        CP16(d, s); CP16(d + 16, s + 16); CP16(d + 32, s + 32); CP16(d + 48, s + 48);
    }
    CP_COMMIT(); CP_WAIT(0);
    __syncthreads();

    const char* Ath = smem + NOFF_A + (rb + gid) * ARB + tig * 4;
    const uint2* Wt = (const uint2*)(smem + NOFF_W) + cq * 128 + lane;

    float acc[2][4][4];
    #pragma unroll
    for (int ch = 0; ch < 2; ch++) {
        ZACC(acc);
        seg<8>(Ath, Wt + ch * 8 * 512, acc);
        #pragma unroll
        for (int mt = 0; mt < 2; mt++) {
            int node0 = blockIdx.x * 128 + rb + mt * 16 + gid;
            int pcol = ch * 64 + (cbase >> 1) + tig;
            #pragma unroll
            for (int nt = 0; nt < 4; nt++) {
                if (node0 < N)
                    g_P[(long long)node0 * 128 + pcol + nt * 4] =
                        f22h2(acc[mt][nt][0], acc[mt][nt][1]);
                if (node0 + 8 < N)
                    g_P[(long long)(node0 + 8) * 128 + pcol + nt * 4] =
                        f22h2(acc[mt][nt][2], acc[mt][nt][3]);
            }
        }
    }
}

// ---- edge kernel: 256 threads, 64-edge tiles, 2 CTAs/SM ----
__global__ void __launch_bounds__(NT, 2)
edge_kernel(const int* __restrict__ ei, const float* __restrict__ ea,
            const float* __restrict__ b1, const float* __restrict__ b2,
            const float* __restrict__ gamma, const float* __restrict__ beta,
            const float* __restrict__ mean, const float* __restrict__ var,
            const float* __restrict__ b3,
            float* __restrict__ out, int E, int ntiles)
{
    extern __shared__ char smem[];
    const unsigned sb = smem_u32(smem);
    int*   sIdx   = (int*)(smem + OFF_IDX);          // [2][128]
    float* sScale = (float*)(smem + OFF_SC);
    float* sShift = (float*)(smem + OFF_SC + 512);
    float* sB1    = (float*)(smem + OFF_SC + 1024);
    float* sB3    = (float*)(smem + OFF_SC + 1536);
    char* B0 = smem + OFF_B0;
    char* B1 = smem + OFF_B1;
    const unsigned* __restrict__ gP = g_P;

    const int tid = threadIdx.x;
    const int w = tid >> 5, lane = tid & 31;
    const int gid = lane >> 2, tig = lane & 3;
    const int rb = (w >> 2) * 32, cq = w & 3, cbase = cq * 32;
    const int r4 = tid >> 2, q4 = tid & 3;

    if (tid < 128) {
        float sc = gamma[tid] * rsqrtf(var[tid] + 1e-5f);
        sScale[tid] = sc;
        sShift[tid] = (b2[tid] - mean[tid]) * sc + beta[tid];
        sB1[tid] = b1[tid];
        sB3[tid] = b3[tid];
    }
    // resident weights: W1 + W2c2 + W3
    {
        #pragma unroll
        for (int i = 0; i < 2; i++)
            CP16(sb + OFF_W1 + (i * NT + tid) * 16, (const char*)g_W1f + (i * NT + tid) * 16);
        #pragma unroll
        for (int i = 0; i < 8; i++)
            CP16(sb + OFF_W2 + (i * NT + tid) * 16,
                 (const char*)(g_W2f + 16 * 512) + (i * NT + tid) * 16);
        #pragma unroll
        for (int i = 0; i < 8; i++)
            CP16(sb + OFF_W3 + (i * NT + tid) * 16, (const char*)g_W3f + (i * NT + tid) * 16);
        CP_COMMIT();
    }
    CP_WAIT(0);
    __syncthreads();

    const bool is64 = ((ei[1] | ei[3] | ei[5] | ei[7]) == 0);
    const long long* ei64 = (const long long*)ei;

    const char* A0th = B0 + (rb + gid) * ARB + tig * 4;
    const char* A1th = B1 + (rb + gid) * ARB + tig * 4;
    const uint2* W1t = (const uint2*)(smem + OFF_W1) + cq * 128 + lane;
    const uint2* W2t = (const uint2*)(smem + OFF_W2) + cq * 128 + lane;
    const uint2* W3t = (const uint2*)(smem + OFF_W3) + cq * 128 + lane;

    #define LOADIDX(slot, eb) { \
        if (tid < 64) { int _e = min((eb) + tid, E - 1); \
            sIdx[(slot) * 128 + tid] = is64 ? (int)ei64[_e] : ei[_e]; \
        } else if (tid < 128) { int _e = min((eb) + tid - 64, E - 1); \
            sIdx[(slot) * 128 + tid] = is64 ? (int)ei64[(long long)E + _e] : ei[E + _e]; } }
    #define LDG_EA(eb, v0, v1) { int _ge = min((eb) + r4, E - 1); \
        const float4* _s = (const float4*)(ea + (long long)_ge * 32) + q4 * 2; \
        v0 = __ldg(_s); v1 = __ldg(_s + 1); }

    int pp = 0;
    const int tile0 = blockIdx.x;
    LOADIDX(0, tile0 * 64);
    __syncthreads();
    float4 ea0, ea1;
    LDG_EA(tile0 * 64, ea0, ea1);

    float acc[2][4][4];

    for (int tile = tile0; tile < ntiles; tile += gridDim.x) {
        const int ebase = tile * 64;
        const int* curIdx = sIdx + pp * 128;
        int nxt = tile + gridDim.x;
        int nebase = (nxt < ntiles ? nxt : tile) * 64;

        // 0. P gather into regs (consumed at epi2; latency hidden by MMA1/2)
        unsigned pr[16], pc[16];
        {
            int pcol = (cbase >> 1) + tig;
            #pragma unroll
            for (int mt = 0; mt < 2; mt++)
                #pragma unroll
                for (int rr = 0; rr < 2; rr++) {
                    int le = rb + mt * 16 + rr * 8 + gid;
                    long long nr = curIdx[le], nc = curIdx[64 + le];
                    #pragma unroll
                    for (int nt = 0; nt < 4; nt++) {
                        int i = mt * 8 + rr * 4 + nt;
                        pr[i] = gP[nr * 128 + pcol + nt * 4];
                        pc[i] = gP[nc * 128 + 64 + pcol + nt * 4];
                    }
                }
        }

        // 1. EA regs -> fp16 -> B1 cols 0..31
        {
            uint4 u;
            u.x = f22h2(ea0.x, ea0.y); u.y = f22h2(ea0.z, ea0.w);
            u.z = f22h2(ea1.x, ea1.y); u.w = f22h2(ea1.z, ea1.w);
            *(uint4*)(B1 + r4 * ARB + q4 * 16) = u;
        }
        __syncthreads();

        // 2. MMA1: e = EA @ W1
        ZACC(acc);
        seg<2>(A1th, W1t, acc);
        __syncthreads();

        // 3. epi1: tanh -> B1
        #pragma unroll
        for (int mt = 0; mt < 2; mt++) {
            int r = rb + mt * 16 + gid;
            #pragma unroll
            for (int nt = 0; nt < 4; nt++) {
                int c = cbase + nt * 8 + tig * 2;
                float blo = sB1[c], bhi = sB1[c + 1];
                *(unsigned*)(B1 + r * ARB + c * 2) =
                    f22h2(fast_tanh(acc[mt][nt][0] + blo), fast_tanh(acc[mt][nt][1] + bhi));
                *(unsigned*)(B1 + (r + 8) * ARB + c * 2) =
                    f22h2(fast_tanh(acc[mt][nt][2] + blo), fast_tanh(acc[mt][nt][3] + bhi));
            }
        }
        __syncthreads();

        // 4. MMA2: e @ W2c2
        ZACC(acc);
        seg<8>(A1th, W2t, acc);
        __syncthreads();                    // B1 free

        // 5. next-tile prefetch: idx + EA regs
        LOADIDX(pp ^ 1, nebase);
        LDG_EA(nebase, ea0, ea1);

        // 6. epi2: h = relu((acc + pr + pc)*scale + shift) -> B0
        #pragma unroll
        for (int mt = 0; mt < 2; mt++) {
            int r = rb + mt * 16 + gid;
            #pragma unroll
            for (int nt = 0; nt < 4; nt++) {
                int c = cbase + nt * 8 + tig * 2;
                float sc0 = sScale[c], sc1 = sScale[c + 1];
                float sh0 = sShift[c], sh1 = sShift[c + 1];
                float2 r0 = h2f2(pr[mt * 8 + nt]),     c0 = h2f2(pc[mt * 8 + nt]);
                float2 r1 = h2f2(pr[mt * 8 + 4 + nt]), c1 = h2f2(pc[mt * 8 + 4 + nt]);
                *(unsigned*)(B0 + r * ARB + c * 2) = f22h2(
                    fmaxf(fmaf(acc[mt][nt][0] + r0.x + c0.x, sc0, sh0), 0.f),
                    fmaxf(fmaf(acc[mt][nt][1] + r0.y + c0.y, sc1, sh1), 0.f));
                *(unsigned*)(B0 + (r + 8) * ARB + c * 2) = f22h2(
                    fmaxf(fmaf(acc[mt][nt][2] + r1.x + c1.x, sc0, sh0), 0.f),
                    fmaxf(fmaf(acc[mt][nt][3] + r1.y + c1.y, sc1, sh1), 0.f));
            }
        }
        __syncthreads();

        // 7. MMA3: y = h @ W3
        ZACC(acc);
        seg<8>(A0th, W3t, acc);

        // 8. epi3: relu(y + b3) -> gmem
        #pragma unroll
        for (int mt = 0; mt < 2; mt++) {
            int r = rb + mt * 16 + gid;
            int e0 = ebase + r, e1 = e0 + 8;
            float* po0 = out + (long long)e0 * 128;
            float* po1 = out + (long long)e1 * 128;
            #pragma unroll
            for (int nt = 0; nt < 4; nt++) {
                int c = cbase + nt * 8 + tig * 2;
                float blo = sB3[c], bhi = sB3[c + 1];
                if (e0 < E) st_cs_v2(po0 + c, fmaxf(acc[mt][nt][0] + blo, 0.f),
                                              fmaxf(acc[mt][nt][1] + bhi, 0.f));
                if (e1 < E) st_cs_v2(po1 + c, fmaxf(acc[mt][nt][2] + blo, 0.f),
                                              fmaxf(acc[mt][nt][3] + bhi, 0.f));
            }
        }
        pp ^= 1;
    }
}

extern "C" void kernel_launch(void* const* d_in, const int* in_sizes, int n_in,
                              void* d_out, int out_size) {
    const float* x     = (const float*)d_in[0];
    const int*   ei    = (const int*)  d_in[1];
    const float* eattr = (const float*)d_in[2];
    const float* W1    = (const float*)d_in[3];
    const float* b1    = (const float*)d_in[4];
    const float* W2    = (const float*)d_in[5];
    const float* b2    = (const float*)d_in[6];
    const float* gam   = (const float*)d_in[7];
    const float* bet   = (const float*)d_in[8];
    const float* mean  = (const float*)d_in[9];
    const float* var   = (const float*)d_in[10];
    const float* W3    = (const float*)d_in[11];
    const float* b3    = (const float*)d_in[12];
    float* out = (float*)d_out;

    int N = in_sizes[0] / 128;
    int E = in_sizes[2] / 32;
    int ntiles = (E + 63) / 64;
    int nblocks = (N + 127) / 128;

    cudaFuncSetAttribute(node_proj, cudaFuncAttributeMaxDynamicSharedMemorySize, SMEM_N);
    cudaFuncSetAttribute(edge_kernel, cudaFuncAttributeMaxDynamicSharedMemorySize, SMEM_E);

    prep<<<1024, 256>>>(x, W1, W2, W3, N);
    node_proj<<<nblocks, 512, SMEM_N>>>(N);
    edge_kernel<<<296, NT, SMEM_E>>>(ei, eattr, b1, b2, gam, bet,
                                     mean, var, b3, out, E, ntiles);
}

// round 11
// speedup vs baseline: 9.7244x; 1.0202x over previous
#include <cuda_runtime.h>
#include <cuda_fp16.h>

#define NT 256
#define ARB 272            // A row stride in bytes (136 halfs)

// ---- edge-kernel smem layout (bytes) ----
#define OFF_IDX  0         // 2 slots x 128 ints = 1024
#define OFF_SC   1024      // scale,shift,b1,b3 = 2048
#define OFF_W1   3072      // 8192
#define OFF_W2   11264     // 32768 (W2 chunk2 frags)
#define OFF_W3   44032     // 32768
#define OFF_B0   76800     // 17408 (64 rows x 136 halfs)
#define OFF_B1   94208     // 17408
#define SMEM_E   111616

// ---- node-kernel smem layout ----
#define NOFF_A   0         // 34816 (128 rows fp16)
#define NOFF_W   34816     // 65536 (W2 c0+c1 frags)
#define NOFF_XS  100352    // 65536 (x fp32 staging)
#define SMEM_N   165888

// ---- device scratch ----
__device__ __align__(16) unsigned g_P[131072 * 128];    // P[n] = x[n]@[W2c0|W2c1], fp16x2
__device__ __align__(16) uint2 g_W1f[2 * 512];
__device__ __align__(16) uint2 g_W2f[24 * 512];
__device__ __align__(16) uint2 g_W3f[8 * 512];

#define CP16(dst, src)  asm volatile("cp.async.cg.shared.global [%0], [%1], 16;" :: "r"(dst), "l"(src) : "memory")
#define CP_COMMIT()     asm volatile("cp.async.commit_group;" ::: "memory")
#define CP_WAIT(n)      asm volatile("cp.async.wait_group %0;" :: "n"(n) : "memory")

__device__ __forceinline__ unsigned smem_u32(const void* p) {
    unsigned a;
    asm("{ .reg .u64 t; cvta.to.shared.u64 t, %1; cvt.u32.u64 %0, t; }" : "=r"(a) : "l"(p));
    return a;
}
__device__ __forceinline__ unsigned f22h2(float lo, float hi) {
    unsigned r;
    asm("cvt.rn.f16x2.f32 %0, %1, %2;" : "=r"(r) : "f"(hi), "f"(lo));
    return r;
}
__device__ __forceinline__ float2 h2f2(unsigned u) {
    __half2 h; *(unsigned*)&h = u;
    return __half22float2(h);
}
__device__ __forceinline__ void mma16(float* c, unsigned a0, unsigned a1, unsigned a2,
                                      unsigned a3, unsigned b0, unsigned b1) {
    asm volatile("mma.sync.aligned.m16n8k16.row.col.f32.f16.f16.f32 "
        "{%0,%1,%2,%3}, {%4,%5,%6,%7}, {%8,%9}, {%0,%1,%2,%3};"
        : "+f"(c[0]), "+f"(c[1]), "+f"(c[2]), "+f"(c[3])
        : "r"(a0), "r"(a1), "r"(a2), "r"(a3), "r"(b0), "r"(b1));
}
__device__ __forceinline__ float tanh_mufu(float v) {
    float r;
    asm("tanh.approx.f32 %0, %1;" : "=f"(r) : "f"(v));
    return r;
}
__device__ __forceinline__ void st_cs_v2(float* p, float a, float b) {
    asm volatile("st.global.cs.v2.f32 [%0], {%1,%2};" :: "l"(p), "f"(a), "f"(b) : "memory");
}

// warp GEMM segment: acc[2][4][4] += A[32 x 16*KS] * W (frag-major)
template<int KS>
__device__ __forceinline__ void seg(const char* Ab, const uint2* Wt, float acc[2][4][4]) {
    #pragma unroll
    for (int ks = 0; ks < KS; ks++) {
        unsigned a[2][4];
        #pragma unroll
        for (int mt = 0; mt < 2; mt++) {
            const char* Am = Ab + ks * 32 + mt * 16 * ARB;
            a[mt][0] = *(const unsigned*)(Am);
            a[mt][1] = *(const unsigned*)(Am + 8 * ARB);
            a[mt][2] = *(const unsigned*)(Am + 16);
            a[mt][3] = *(const unsigned*)(Am + 8 * ARB + 16);
        }
        const uint2* Bk = Wt + ks * 512;
        #pragma unroll
        for (int nt = 0; nt < 4; nt++) {
            uint2 b = Bk[nt * 32];
            mma16(acc[0][nt], a[0][0], a[0][1], a[0][2], a[0][3], b.x, b.y);
            mma16(acc[1][nt], a[1][0], a[1][1], a[1][2], a[1][3], b.x, b.y);
        }
    }
}

#define ZACC(a) { _Pragma("unroll") for (int _m = 0; _m < 2; _m++) \
    _Pragma("unroll") for (int _n = 0; _n < 4; _n++) { \
    (a)[_m][_n][0]=0.f;(a)[_m][_n][1]=0.f;(a)[_m][_n][2]=0.f;(a)[_m][_n][3]=0.f; } }

// ---- prep: weights -> fragment-major fp16 (weights only; tiny) ----
__global__ void prep(const float* __restrict__ W1, const float* __restrict__ W2,
                     const float* __restrict__ W3) {
    int t = blockIdx.x * blockDim.x + threadIdx.x;
    int s = gridDim.x * blockDim.x;
    for (int i = t; i < 2 * 512; i += s) {
        int lane = i & 31, nt = (i >> 5) & 3, cq = (i >> 7) & 3, ks = i >> 9;
        int n = cq * 32 + nt * 8 + (lane >> 2), k0 = ks * 16 + (lane & 3) * 2;
        g_W1f[i] = make_uint2(f22h2(W1[k0 * 128 + n], W1[(k0 + 1) * 128 + n]),
                              f22h2(W1[(k0 + 8) * 128 + n], W1[(k0 + 9) * 128 + n]));
    }
    for (int i = t; i < 24 * 512; i += s) {
        int lane = i & 31, nt = (i >> 5) & 3, cq = (i >> 7) & 3, ks = i >> 9;
        int n = cq * 32 + nt * 8 + (lane >> 2), k0 = ks * 16 + (lane & 3) * 2;
        g_W2f[i] = make_uint2(f22h2(W2[k0 * 128 + n], W2[(k0 + 1) * 128 + n]),
                              f22h2(W2[(k0 + 8) * 128 + n], W2[(k0 + 9) * 128 + n]));
    }
    for (int i = t; i < 8 * 512; i += s) {
        int lane = i & 31, nt = (i >> 5) & 3, cq = (i >> 7) & 3, ks = i >> 9;
        int n = cq * 32 + nt * 8 + (lane >> 2), k0 = ks * 16 + (lane & 3) * 2;
        g_W3f[i] = make_uint2(f22h2(W3[k0 * 128 + n], W3[(k0 + 1) * 128 + n]),
                              f22h2(W3[(k0 + 8) * 128 + n], W3[(k0 + 9) * 128 + n]));
    }
}

// ---- node projections: P[n] = x[n] @ [W2c0 | W2c1] (x read fp32, converted here) ----
__global__ void __launch_bounds__(512, 1)
node_proj(const float* __restrict__ x, int N) {
    extern __shared__ char smem[];
    const unsigned sb = smem_u32(smem);
    const int tid = threadIdx.x;
    const int w = tid >> 5, lane = tid & 31;
    const int gid = lane >> 2, tig = lane & 3;
    const int rb = (w >> 2) * 32, cq = w & 3, cbase = cq * 32;
    const int r4 = tid >> 2, q4 = tid & 3;

    #pragma unroll
    for (int i = 0; i < 8; i++)
        CP16(sb + NOFF_W + (i * 512 + tid) * 16, (const char*)g_W2f + (i * 512 + tid) * 16);
    {
        int node = min(blockIdx.x * 128 + r4, N - 1);
        const float* s = x + (long long)node * 128 + q4 * 32;
        unsigned d = sb + NOFF_XS + (r4 * 128 + q4 * 32) * 4;
        #pragma unroll
        for (int i = 0; i < 8; i++) CP16(d + i * 16, s + i * 4);
    }
    CP_COMMIT(); CP_WAIT(0);
    __syncthreads();

    // convert x fp32 -> fp16 into A
    {
        const float* s = (const float*)(smem + NOFF_XS) + r4 * 128 + q4 * 32;
        unsigned* d = (unsigned*)(smem + NOFF_A + r4 * ARB) + q4 * 16;
        #pragma unroll
        for (int i = 0; i < 16; i++) d[i] = f22h2(s[2 * i], s[2 * i + 1]);
    }
    __syncthreads();

    const char* Ath = smem + NOFF_A + (rb + gid) * ARB + tig * 4;
    const uint2* Wt = (const uint2*)(smem + NOFF_W) + cq * 128 + lane;

    float acc[2][4][4];
    #pragma unroll
    for (int ch = 0; ch < 2; ch++) {
        ZACC(acc);
        seg<8>(Ath, Wt + ch * 8 * 512, acc);
        #pragma unroll
        for (int mt = 0; mt < 2; mt++) {
            int node0 = blockIdx.x * 128 + rb + mt * 16 + gid;
            int pcol = ch * 64 + (cbase >> 1) + tig;
            #pragma unroll
            for (int nt = 0; nt < 4; nt++) {
                if (node0 < N)
                    g_P[(long long)node0 * 128 + pcol + nt * 4] =
                        f22h2(acc[mt][nt][0], acc[mt][nt][1]);
                if (node0 + 8 < N)
                    g_P[(long long)(node0 + 8) * 128 + pcol + nt * 4] =
                        f22h2(acc[mt][nt][2], acc[mt][nt][3]);
            }
        }
    }
}

// ---- edge kernel: 256 threads, 64-edge tiles, 2 CTAs/SM, 2 independent row groups ----
__global__ void __launch_bounds__(NT, 2)
edge_kernel(const int* __restrict__ ei, const float* __restrict__ ea,
            const float* __restrict__ b1, const float* __restrict__ b2,
            const float* __restrict__ gamma, const float* __restrict__ beta,
            const float* __restrict__ mean, const float* __restrict__ var,
            const float* __restrict__ b3,
            float* __restrict__ out, int E, int ntiles)
{
    extern __shared__ char smem[];
    const unsigned sb = smem_u32(smem);
    int*   sIdx   = (int*)(smem + OFF_IDX);          // [2][128]
    float* sScale = (float*)(smem + OFF_SC);
    float* sShift = (float*)(smem + OFF_SC + 512);
    float* sB1    = (float*)(smem + OFF_SC + 1024);
    float* sB3    = (float*)(smem + OFF_SC + 1536);
    char* B0 = smem + OFF_B0;
    char* B1 = smem + OFF_B1;
    const unsigned* __restrict__ gP = g_P;

    const int tid = threadIdx.x;
    const int w = tid >> 5, lane = tid & 31;
    const int gid = lane >> 2, tig = lane & 3;
    const int rb = (w >> 2) * 32, cq = w & 3, cbase = cq * 32;
    const int r4 = tid >> 2, q4 = tid & 3;
    const int grp = tid >> 7;                        // row group (0: rows 0-31, 1: rows 32-63)

    // group-scoped barrier: only the 128 threads of this row group
    #define GBAR() asm volatile("bar.sync %0, 128;" :: "r"(grp + 1) : "memory")

    if (tid < 128) {
        float sc = gamma[tid] * rsqrtf(var[tid] + 1e-5f);
        sScale[tid] = sc;
        sShift[tid] = (b2[tid] - mean[tid]) * sc + beta[tid];
        sB1[tid] = b1[tid];
        sB3[tid] = b3[tid];
    }
    // resident weights: W1 + W2c2 + W3
    {
        #pragma unroll
        for (int i = 0; i < 2; i++)
            CP16(sb + OFF_W1 + (i * NT + tid) * 16, (const char*)g_W1f + (i * NT + tid) * 16);
        #pragma unroll
        for (int i = 0; i < 8; i++)
            CP16(sb + OFF_W2 + (i * NT + tid) * 16,
                 (const char*)(g_W2f + 16 * 512) + (i * NT + tid) * 16);
        #pragma unroll
        for (int i = 0; i < 8; i++)
            CP16(sb + OFF_W3 + (i * NT + tid) * 16, (const char*)g_W3f + (i * NT + tid) * 16);
        CP_COMMIT();
    }
    CP_WAIT(0);
    __syncthreads();

    const bool is64 = ((ei[1] | ei[3] | ei[5] | ei[7]) == 0);
    const long long* ei64 = (const long long*)ei;

    const char* A0th = B0 + (rb + gid) * ARB + tig * 4;
    const char* A1th = B1 + (rb + gid) * ARB + tig * 4;
    const uint2* W1t = (const uint2*)(smem + OFF_W1) + cq * 128 + lane;
    const uint2* W2t = (const uint2*)(smem + OFF_W2) + cq * 128 + lane;
    const uint2* W3t = (const uint2*)(smem + OFF_W3) + cq * 128 + lane;

    // group-local index load: group g loads its own 32 row-idx + 32 col-idx
    #define LOADIDX(slot, eb) { int _lt = tid & 127; \
        if (_lt < 32) { int _e = min((eb) + grp * 32 + _lt, E - 1); \
            sIdx[(slot) * 128 + grp * 32 + _lt] = is64 ? (int)ei64[_e] : ei[_e]; \
        } else if (_lt < 64) { int _e = min((eb) + grp * 32 + (_lt - 32), E - 1); \
            sIdx[(slot) * 128 + 64 + grp * 32 + (_lt - 32)] = \
                is64 ? (int)ei64[(long long)E + _e] : ei[E + _e]; } }
    #define LDG_EA(eb, v0, v1) { int _ge = min((eb) + r4, E - 1); \
        const float4* _s = (const float4*)(ea + (long long)_ge * 32) + q4 * 2; \
        v0 = __ldg(_s); v1 = __ldg(_s + 1); }

    int pp = 0;
    const int tile0 = blockIdx.x;
    LOADIDX(0, tile0 * 64);
    __syncthreads();
    float4 ea0, ea1;
    LDG_EA(tile0 * 64, ea0, ea1);

    float acc[2][4][4];

    for (int tile = tile0; tile < ntiles; tile += gridDim.x) {
        const int ebase = tile * 64;
        const int* curIdx = sIdx + pp * 128;
        int nxt = tile + gridDim.x;
        int nebase = (nxt < ntiles ? nxt : tile) * 64;

        // 0. P gather into regs (consumed at epi2)
        unsigned pr[16], pc[16];
        {
            int pcol = (cbase >> 1) + tig;
            #pragma unroll
            for (int mt = 0; mt < 2; mt++)
                #pragma unroll
                for (int rr = 0; rr < 2; rr++) {
                    int le = rb + mt * 16 + rr * 8 + gid;
                    long long nr = curIdx[le], nc = curIdx[64 + le];
                    #pragma unroll
                    for (int nt = 0; nt < 4; nt++) {
                        int i = mt * 8 + rr * 4 + nt;
                        pr[i] = gP[nr * 128 + pcol + nt * 4];
                        pc[i] = gP[nc * 128 + 64 + pcol + nt * 4];
                    }
                }
        }

        // 1. EA regs -> fp16 -> B1 cols 0..31 (group-local rows)
        {
            uint4 u;
            u.x = f22h2(ea0.x, ea0.y); u.y = f22h2(ea0.z, ea0.w);
            u.z = f22h2(ea1.x, ea1.y); u.w = f22h2(ea1.z, ea1.w);
            *(uint4*)(B1 + r4 * ARB + q4 * 16) = u;
        }
        GBAR();

        // 2. MMA1: e = EA @ W1
        ZACC(acc);
        seg<2>(A1th, W1t, acc);
        GBAR();

        // 3. epi1: tanh (MUFU) -> B1
        #pragma unroll
        for (int mt = 0; mt < 2; mt++) {
            int r = rb + mt * 16 + gid;
            #pragma unroll
            for (int nt = 0; nt < 4; nt++) {
                int c = cbase + nt * 8 + tig * 2;
                float blo = sB1[c], bhi = sB1[c + 1];
                *(unsigned*)(B1 + r * ARB + c * 2) =
                    f22h2(tanh_mufu(acc[mt][nt][0] + blo), tanh_mufu(acc[mt][nt][1] + bhi));
                *(unsigned*)(B1 + (r + 8) * ARB + c * 2) =
                    f22h2(tanh_mufu(acc[mt][nt][2] + blo), tanh_mufu(acc[mt][nt][3] + bhi));
            }
        }
        GBAR();

        // 4. MMA2: e @ W2c2
        ZACC(acc);
        seg<8>(A1th, W2t, acc);
        GBAR();                             // B1 free (this group's rows)

        // 5. next-tile prefetch: idx + EA regs
        LOADIDX(pp ^ 1, nebase);
        LDG_EA(nebase, ea0, ea1);

        // 6. epi2: h = relu((acc + pr + pc)*scale + shift) -> B0
        #pragma unroll
        for (int mt = 0; mt < 2; mt++) {
            int r = rb + mt * 16 + gid;
            #pragma unroll
            for (int nt = 0; nt < 4; nt++) {
                int c = cbase + nt * 8 + tig * 2;
                float sc0 = sScale[c], sc1 = sScale[c + 1];
                float sh0 = sShift[c], sh1 = sShift[c + 1];
                float2 r0 = h2f2(pr[mt * 8 + nt]),     c0 = h2f2(pc[mt * 8 + nt]);
                float2 r1 = h2f2(pr[mt * 8 + 4 + nt]), c1 = h2f2(pc[mt * 8 + 4 + nt]);
                *(unsigned*)(B0 + r * ARB + c * 2) = f22h2(
                    fmaxf(fmaf(acc[mt][nt][0] + r0.x + c0.x, sc0, sh0), 0.f),
                    fmaxf(fmaf(acc[mt][nt][1] + r0.y + c0.y, sc1, sh1), 0.f));
                *(unsigned*)(B0 + (r + 8) * ARB + c * 2) = f22h2(
                    fmaxf(fmaf(acc[mt][nt][2] + r1.x + c1.x, sc0, sh0), 0.f),
                    fmaxf(fmaf(acc[mt][nt][3] + r1.y + c1.y, sc1, sh1), 0.f));
            }
        }
        GBAR();

        // 7. MMA3: y = h @ W3
        ZACC(acc);
        seg<8>(A0th, W3t, acc);

        // 8. epi3: relu(y + b3) -> gmem
        #pragma unroll
        for (int mt = 0; mt < 2; mt++) {
            int r = rb + mt * 16 + gid;
            int e0 = ebase + r, e1 = e0 + 8;
            float* po0 = out + (long long)e0 * 128;
            float* po1 = out + (long long)e1 * 128;
            #pragma unroll
            for (int nt = 0; nt < 4; nt++) {
                int c = cbase + nt * 8 + tig * 2;
                float blo = sB3[c], bhi = sB3[c + 1];
                if (e0 < E) st_cs_v2(po0 + c, fmaxf(acc[mt][nt][0] + blo, 0.f),
                                              fmaxf(acc[mt][nt][1] + bhi, 0.f));
                if (e1 < E) st_cs_v2(po1 + c, fmaxf(acc[mt][nt][2] + blo, 0.f),
                                              fmaxf(acc[mt][nt][3] + bhi, 0.f));
            }
        }
        pp ^= 1;
    }
}

extern "C" void kernel_launch(void* const* d_in, const int* in_sizes, int n_in,
                              void* d_out, int out_size) {
    const float* x     = (const float*)d_in[0];
    const int*   ei    = (const int*)  d_in[1];
    const float* eattr = (const float*)d_in[2];
    const float* W1    = (const float*)d_in[3];
    const float* b1    = (const float*)d_in[4];
    const float* W2    = (const float*)d_in[5];
    const float* b2    = (const float*)d_in[6];
    const float* gam   = (const float*)d_in[7];
    const float* bet   = (const float*)d_in[8];
    const float* mean  = (const float*)d_in[9];
    const float* var   = (const float*)d_in[10];
    const float* W3    = (const float*)d_in[11];
    const float* b3    = (const float*)d_in[12];
    float* out = (float*)d_out;

    int N = in_sizes[0] / 128;
    int E = in_sizes[2] / 32;
    int ntiles = (E + 63) / 64;
    int nblocks = (N + 127) / 128;

    cudaFuncSetAttribute(node_proj, cudaFuncAttributeMaxDynamicSharedMemorySize, SMEM_N);
    cudaFuncSetAttribute(edge_kernel, cudaFuncAttributeMaxDynamicSharedMemorySize, SMEM_E);

    prep<<<64, 256>>>(W1, W2, W3);
    node_proj<<<nblocks, 512, SMEM_N>>>(x, N);
    edge_kernel<<<296, NT, SMEM_E>>>(ei, eattr, b1, b2, gam, bet,
                                     mean, var, b3, out, E, ntiles);
}

// round 12
// speedup vs baseline: 11.0696x; 1.1383x over previous
#include <cuda_runtime.h>
#include <cuda_fp16.h>

#define NT 512
#define ARB 272            // A row stride bytes (136 halfs)
#define PRB 272            // P staging row stride bytes

// ---- edge-kernel smem layout (bytes) ----
#define OFF_IDX  0         // 4 groups x 2 slots x 64 ints = 2048
#define OFF_SC   2048      // scale,shift,b1,b3 = 2048
#define OFF_W1   4096      // 8192
#define OFF_W2   12288     // 32768 (W2 chunk2 frags)
#define OFF_W3   45056     // 32768
#define OFF_A    77824     // 34816 (128 rows x 272B)
#define OFF_PR   112640    // 34816 (row-proj staging)
#define OFF_PC   147456    // 34816 (col-proj staging)
#define SMEM_E   182272

// ---- node-kernel smem layout ----
#define NOFF_A   0         // 34816 (128 rows fp16)
#define NOFF_W   34816     // 65536 (W2 c0+c1 frags)
#define NOFF_XS  100352    // 65536 (x fp32 staging)
#define SMEM_N   165888

// ---- device scratch ----
__device__ __align__(16) unsigned g_P[131072 * 128];    // P[n] = x[n]@[W2c0|W2c1], fp16x2
__device__ __align__(16) uint2 g_W1f[2 * 512];
__device__ __align__(16) uint2 g_W2f[24 * 512];
__device__ __align__(16) uint2 g_W3f[8 * 512];

#define CP16(dst, src)  asm volatile("cp.async.cg.shared.global [%0], [%1], 16;" :: "r"(dst), "l"(src) : "memory")
#define CP_COMMIT()     asm volatile("cp.async.commit_group;" ::: "memory")
#define CP_WAIT(n)      asm volatile("cp.async.wait_group %0;" :: "n"(n) : "memory")

__device__ __forceinline__ unsigned smem_u32(const void* p) {
    unsigned a;
    asm("{ .reg .u64 t; cvta.to.shared.u64 t, %1; cvt.u32.u64 %0, t; }" : "=r"(a) : "l"(p));
    return a;
}
__device__ __forceinline__ unsigned f22h2(float lo, float hi) {
    unsigned r;
    asm("cvt.rn.f16x2.f32 %0, %1, %2;" : "=r"(r) : "f"(hi), "f"(lo));
    return r;
}
__device__ __forceinline__ float2 h2f2(unsigned u) {
    __half2 h; *(unsigned*)&h = u;
    return __half22float2(h);
}
__device__ __forceinline__ void mma16(float* c, unsigned a0, unsigned a1, unsigned a2,
                                      unsigned a3, unsigned b0, unsigned b1) {
    asm volatile("mma.sync.aligned.m16n8k16.row.col.f32.f16.f16.f32 "
        "{%0,%1,%2,%3}, {%4,%5,%6,%7}, {%8,%9}, {%0,%1,%2,%3};"
        : "+f"(c[0]), "+f"(c[1]), "+f"(c[2]), "+f"(c[3])
        : "r"(a0), "r"(a1), "r"(a2), "r"(a3), "r"(b0), "r"(b1));
}
__device__ __forceinline__ float tanh_mufu(float v) {
    float r;
    asm("tanh.approx.f32 %0, %1;" : "=f"(r) : "f"(v));
    return r;
}
__device__ __forceinline__ void st_cs_v2(float* p, float a, float b) {
    asm volatile("st.global.cs.v2.f32 [%0], {%1,%2};" :: "l"(p), "f"(a), "f"(b) : "memory");
}

// warp GEMM segment: acc[2][4][4] += A[32 x 16*KS] * W (frag-major)
template<int KS>
__device__ __forceinline__ void seg(const char* Ab, const uint2* Wt, float acc[2][4][4]) {
    #pragma unroll
    for (int ks = 0; ks < KS; ks++) {
        unsigned a[2][4];
        #pragma unroll
        for (int mt = 0; mt < 2; mt++) {
            const char* Am = Ab + ks * 32 + mt * 16 * ARB;
            a[mt][0] = *(const unsigned*)(Am);
            a[mt][1] = *(const unsigned*)(Am + 8 * ARB);
            a[mt][2] = *(const unsigned*)(Am + 16);
            a[mt][3] = *(const unsigned*)(Am + 8 * ARB + 16);
        }
        const uint2* Bk = Wt + ks * 512;
        #pragma unroll
        for (int nt = 0; nt < 4; nt++) {
            uint2 b = Bk[nt * 32];
            mma16(acc[0][nt], a[0][0], a[0][1], a[0][2], a[0][3], b.x, b.y);
            mma16(acc[1][nt], a[1][0], a[1][1], a[1][2], a[1][3], b.x, b.y);
        }
    }
}

#define ZACC(a) { _Pragma("unroll") for (int _m = 0; _m < 2; _m++) \
    _Pragma("unroll") for (int _n = 0; _n < 4; _n++) { \
    (a)[_m][_n][0]=0.f;(a)[_m][_n][1]=0.f;(a)[_m][_n][2]=0.f;(a)[_m][_n][3]=0.f; } }

// ---- prep: weights -> fragment-major fp16 ----
__global__ void prep(const float* __restrict__ W1, const float* __restrict__ W2,
                     const float* __restrict__ W3) {
    int t = blockIdx.x * blockDim.x + threadIdx.x;
    int s = gridDim.x * blockDim.x;
    for (int i = t; i < 2 * 512; i += s) {
        int lane = i & 31, nt = (i >> 5) & 3, cq = (i >> 7) & 3, ks = i >> 9;
        int n = cq * 32 + nt * 8 + (lane >> 2), k0 = ks * 16 + (lane & 3) * 2;
        g_W1f[i] = make_uint2(f22h2(W1[k0 * 128 + n], W1[(k0 + 1) * 128 + n]),
                              f22h2(W1[(k0 + 8) * 128 + n], W1[(k0 + 9) * 128 + n]));
    }
    for (int i = t; i < 24 * 512; i += s) {
        int lane = i & 31, nt = (i >> 5) & 3, cq = (i >> 7) & 3, ks = i >> 9;
        int n = cq * 32 + nt * 8 + (lane >> 2), k0 = ks * 16 + (lane & 3) * 2;
        g_W2f[i] = make_uint2(f22h2(W2[k0 * 128 + n], W2[(k0 + 1) * 128 + n]),
                              f22h2(W2[(k0 + 8) * 128 + n], W2[(k0 + 9) * 128 + n]));
    }
    for (int i = t; i < 8 * 512; i += s) {
        int lane = i & 31, nt = (i >> 5) & 3, cq = (i >> 7) & 3, ks = i >> 9;
        int n = cq * 32 + nt * 8 + (lane >> 2), k0 = ks * 16 + (lane & 3) * 2;
        g_W3f[i] = make_uint2(f22h2(W3[k0 * 128 + n], W3[(k0 + 1) * 128 + n]),
                              f22h2(W3[(k0 + 8) * 128 + n], W3[(k0 + 9) * 128 + n]));
    }
}

// ---- node projections: P[n] = x[n] @ [W2c0 | W2c1] ----
__global__ void __launch_bounds__(512, 1)
node_proj(const float* __restrict__ x, int N) {
    extern __shared__ char smem[];
    const unsigned sb = smem_u32(smem);
    const int tid = threadIdx.x;
    const int w = tid >> 5, lane = tid & 31;
    const int gid = lane >> 2, tig = lane & 3;
    const int rb = (w >> 2) * 32, cq = w & 3, cbase = cq * 32;
    const int r4 = tid >> 2, q4 = tid & 3;

    #pragma unroll
    for (int i = 0; i < 8; i++)
        CP16(sb + NOFF_W + (i * 512 + tid) * 16, (const char*)g_W2f + (i * 512 + tid) * 16);
    {
        int node = min(blockIdx.x * 128 + r4, N - 1);
        const float* s = x + (long long)node * 128 + q4 * 32;
        unsigned d = sb + NOFF_XS + (r4 * 128 + q4 * 32) * 4;
        #pragma unroll
        for (int i = 0; i < 8; i++) CP16(d + i * 16, s + i * 4);
    }
    CP_COMMIT(); CP_WAIT(0);
    __syncthreads();

    {
        const float* s = (const float*)(smem + NOFF_XS) + r4 * 128 + q4 * 32;
        unsigned* d = (unsigned*)(smem + NOFF_A + r4 * ARB) + q4 * 16;
        #pragma unroll
        for (int i = 0; i < 16; i++) d[i] = f22h2(s[2 * i], s[2 * i + 1]);
    }
    __syncthreads();

    const char* Ath = smem + NOFF_A + (rb + gid) * ARB + tig * 4;
    const uint2* Wt = (const uint2*)(smem + NOFF_W) + cq * 128 + lane;

    float acc[2][4][4];
    #pragma unroll
    for (int ch = 0; ch < 2; ch++) {
        ZACC(acc);
        seg<8>(Ath, Wt + ch * 8 * 512, acc);
        #pragma unroll
        for (int mt = 0; mt < 2; mt++) {
            int node0 = blockIdx.x * 128 + rb + mt * 16 + gid;
            int pcol = ch * 64 + (cbase >> 1) + tig;
            #pragma unroll
            for (int nt = 0; nt < 4; nt++) {
                if (node0 < N)
                    g_P[(long long)node0 * 128 + pcol + nt * 4] =
                        f22h2(acc[mt][nt][0], acc[mt][nt][1]);
                if (node0 + 8 < N)
                    g_P[(long long)(node0 + 8) * 128 + pcol + nt * 4] =
                        f22h2(acc[mt][nt][2], acc[mt][nt][3]);
            }
        }
    }
}

// ---- edge kernel: 512 threads, 128-edge tiles, 4 independent row-group streams ----
__global__ void __launch_bounds__(NT, 1)
edge_kernel(const int* __restrict__ ei, const float* __restrict__ ea,
            const float* __restrict__ b1, const float* __restrict__ b2,
            const float* __restrict__ gamma, const float* __restrict__ beta,
            const float* __restrict__ mean, const float* __restrict__ var,
            const float* __restrict__ b3,
            float* __restrict__ out, int E, int ntiles)
{
    extern __shared__ char smem[];
    const unsigned sb = smem_u32(smem);
    int*   sIdx   = (int*)(smem + OFF_IDX);          // [4 grp][2 slot][64]
    float* sScale = (float*)(smem + OFF_SC);
    float* sShift = (float*)(smem + OFF_SC + 512);
    float* sB1    = (float*)(smem + OFF_SC + 1024);
    float* sB3    = (float*)(smem + OFF_SC + 1536);

    const int tid = threadIdx.x;
    const int w = tid >> 5, lane = tid & 31;
    const int gid = lane >> 2, tig = lane & 3;
    const int g = w >> 2, cq = w & 3;                // group, column quarter
    const int rb = g * 32, cbase = cq * 32;
    const int lt = tid & 127, lr4 = lt >> 2, q4 = lt & 3;
    const int r4g = rb + lr4;                        // this thread's edge row in tile

    #define GBAR() asm volatile("bar.sync %0, 128;" :: "r"(g + 1) : "memory")

    if (tid < 128) {
        float sc = gamma[tid] * rsqrtf(var[tid] + 1e-5f);
        sScale[tid] = sc;
        sShift[tid] = (b2[tid] - mean[tid]) * sc + beta[tid];
        sB1[tid] = b1[tid];
        sB3[tid] = b3[tid];
    }
    // resident weights: W1 + W2c2 + W3
    {
        CP16(sb + OFF_W1 + tid * 16, (const char*)g_W1f + tid * 16);
        #pragma unroll
        for (int i = 0; i < 4; i++)
            CP16(sb + OFF_W2 + (i * NT + tid) * 16,
                 (const char*)(g_W2f + 16 * 512) + (i * NT + tid) * 16);
        #pragma unroll
        for (int i = 0; i < 4; i++)
            CP16(sb + OFF_W3 + (i * NT + tid) * 16, (const char*)g_W3f + (i * NT + tid) * 16);
        CP_COMMIT();
    }
    CP_WAIT(0);
    __syncthreads();

    const bool is64 = ((ei[1] | ei[3] | ei[5] | ei[7]) == 0);
    const long long* ei64 = (const long long*)ei;

    const char* Ath = smem + OFF_A + (rb + gid) * ARB + tig * 4;
    const uint2* W1t = (const uint2*)(smem + OFF_W1) + cq * 128 + lane;
    const uint2* W2t = (const uint2*)(smem + OFF_W2) + cq * 128 + lane;
    const uint2* W3t = (const uint2*)(smem + OFF_W3) + cq * 128 + lane;

    // group-local index load: 32 row + 32 col for this group's edges
    #define LOADIDX(slot, eb) { \
        if (lt < 32) { int _e = min((eb) + rb + lt, E - 1); \
            sIdx[(g * 2 + (slot)) * 64 + lt] = is64 ? (int)ei64[_e] : ei[_e]; \
        } else if (lt < 64) { int _e = min((eb) + rb + (lt - 32), E - 1); \
            sIdx[(g * 2 + (slot)) * 64 + lt] = is64 ? (int)ei64[(long long)E + _e] : ei[E + _e]; } }
    #define LDG_EA(eb, v0, v1) { int _ge = min((eb) + r4g, E - 1); \
        const float4* _s = (const float4*)(ea + (long long)_ge * 32) + q4 * 2; \
        v0 = __ldg(_s); v1 = __ldg(_s + 1); }

    int pp = 0;
    const int tile0 = blockIdx.x;
    LOADIDX(0, tile0 * 128);
    __syncthreads();
    float4 ea0, ea1;
    LDG_EA(tile0 * 128, ea0, ea1);

    float acc[2][4][4];

    for (int tile = tile0; tile < ntiles; tile += gridDim.x) {
        const int ebase = tile * 128;
        const int* curIdx = sIdx + (g * 2 + pp) * 64;
        int nxt = tile + gridDim.x;
        int nebase = (nxt < ntiles ? nxt : tile) * 128;

        // 0. issue P gather (coalesced cp.async, group-local rows)
        {
            long long nr = curIdx[lr4], nc = curIdx[32 + lr4];
            const char* sR = (const char*)g_P + nr * 512 + q4 * 64;
            const char* sC = (const char*)g_P + nc * 512 + 256 + q4 * 64;
            unsigned dR = sb + OFF_PR + r4g * PRB + q4 * 64;
            unsigned dC = sb + OFF_PC + r4g * PRB + q4 * 64;
            #pragma unroll
            for (int i = 0; i < 4; i++) CP16(dR + i * 16, sR + i * 16);
            #pragma unroll
            for (int i = 0; i < 4; i++) CP16(dC + i * 16, sC + i * 16);
            CP_COMMIT();
        }

        // 1. EA regs -> fp16 -> A cols 0..31
        {
            uint4 u;
            u.x = f22h2(ea0.x, ea0.y); u.y = f22h2(ea0.z, ea0.w);
            u.z = f22h2(ea1.x, ea1.y); u.w = f22h2(ea1.z, ea1.w);
            *(uint4*)(smem + OFF_A + r4g * ARB + q4 * 16) = u;
        }
        GBAR();

        // 2. MMA1: e = EA @ W1
        ZACC(acc);
        seg<2>(Ath, W1t, acc);
        GBAR();

        // 3. epi1: tanh -> A
        #pragma unroll
        for (int mt = 0; mt < 2; mt++) {
            int r = rb + mt * 16 + gid;
            #pragma unroll
            for (int nt = 0; nt < 4; nt++) {
                int c = cbase + nt * 8 + tig * 2;
                float blo = sB1[c], bhi = sB1[c + 1];
                *(unsigned*)(smem + OFF_A + r * ARB + c * 2) =
                    f22h2(tanh_mufu(acc[0][nt][0] + blo), tanh_mufu(acc[0][nt][1] + bhi));
                *(unsigned*)(smem + OFF_A + (r + 8) * ARB + c * 2) =
                    f22h2(tanh_mufu(acc[0][nt][2] + blo), tanh_mufu(acc[0][nt][3] + bhi));
                acc[0][nt][0] = acc[1][nt][0]; acc[0][nt][1] = acc[1][nt][1];
                acc[0][nt][2] = acc[1][nt][2]; acc[0][nt][3] = acc[1][nt][3];
            }
        }
        GBAR();

        // 4. MMA2: e @ W2c2
        ZACC(acc);
        seg<8>(Ath, W2t, acc);

        // 5. prefetch next tile idx + EA; wait P
        LOADIDX(pp ^ 1, nebase);
        LDG_EA(nebase, ea0, ea1);
        CP_WAIT(0);
        GBAR();                              // MMA2 reads done + P visible

        // 6. epi2: h = relu((acc + pr + pc)*scale + shift) -> A
        #pragma unroll
        for (int mt = 0; mt < 2; mt++) {
            #pragma unroll
            for (int nt = 0; nt < 4; nt++) {
                int r = rb + mt * 16 + gid;
                int c = cbase + nt * 8 + tig * 2;
                int word4 = (c >> 1) * 4;
                float sc0 = sScale[c], sc1 = sScale[c + 1];
                float sh0 = sShift[c], sh1 = sShift[c + 1];
                float2 r0 = h2f2(*(const unsigned*)(smem + OFF_PR + r * PRB + word4));
                float2 c0 = h2f2(*(const unsigned*)(smem + OFF_PC + r * PRB + word4));
                float2 r1 = h2f2(*(const unsigned*)(smem + OFF_PR + (r + 8) * PRB + word4));
                float2 c1 = h2f2(*(const unsigned*)(smem + OFF_PC + (r + 8) * PRB + word4));
                *(unsigned*)(smem + OFF_A + r * ARB + c * 2) = f22h2(
                    fmaxf(fmaf(acc[mt][nt][0] + r0.x + c0.x, sc0, sh0), 0.f),
                    fmaxf(fmaf(acc[mt][nt][1] + r0.y + c0.y, sc1, sh1), 0.f));
                *(unsigned*)(smem + OFF_A + (r + 8) * ARB + c * 2) = f22h2(
                    fmaxf(fmaf(acc[mt][nt][2] + r1.x + c1.x, sc0, sh0), 0.f),
                    fmaxf(fmaf(acc[mt][nt][3] + r1.y + c1.y, sc1, sh1), 0.f));
            }
        }
        GBAR();

        // 7. MMA3: y = h @ W3
        ZACC(acc);
        seg<8>(Ath, W3t, acc);

        // 8. epi3: relu(y + b3) -> gmem
        #pragma unroll
        for (int mt = 0; mt < 2; mt++) {
            int r = rb + mt * 16 + gid;
            int e0 = ebase + r, e1 = e0 + 8;
            float* po0 = out + (long long)e0 * 128;
            float* po1 = out + (long long)e1 * 128;
            #pragma unroll
            for (int nt = 0; nt < 4; nt++) {
                int c = cbase + nt * 8 + tig * 2;
                float blo = sB3[c], bhi = sB3[c + 1];
                if (e0 < E) st_cs_v2(po0 + c, fmaxf(acc[mt][nt][0] + blo, 0.f),
                                              fmaxf(acc[mt][nt][1] + bhi, 0.f));
                if (e1 < E) st_cs_v2(po1 + c, fmaxf(acc[mt][nt][2] + blo, 0.f),
                                              fmaxf(acc[mt][nt][3] + bhi, 0.f));
            }
        }
        GBAR();                              // A + P staging free for next tile
        pp ^= 1;
    }
}

extern "C" void kernel_launch(void* const* d_in, const int* in_sizes, int n_in,
                              void* d_out, int out_size) {
    const float* x     = (const float*)d_in[0];
    const int*   ei    = (const int*)  d_in[1];
    const float* eattr = (const float*)d_in[2];
    const float* W1    = (const float*)d_in[3];
    const float* b1    = (const float*)d_in[4];
    const float* W2    = (const float*)d_in[5];
    const float* b2    = (const float*)d_in[6];
    const float* gam   = (const float*)d_in[7];
    const float* bet   = (const float*)d_in[8];
    const float* mean  = (const float*)d_in[9];
    const float* var   = (const float*)d_in[10];
    const float* W3    = (const float*)d_in[11];
    const float* b3    = (const float*)d_in[12];
    float* out = (float*)d_out;

    int N = in_sizes[0] / 128;
    int E = in_sizes[2] / 32;
    int ntiles = (E + 127) / 128;
    int nblocks = (N + 127) / 128;

    cudaFuncSetAttribute(node_proj, cudaFuncAttributeMaxDynamicSharedMemorySize, SMEM_N);
    cudaFuncSetAttribute(edge_kernel, cudaFuncAttributeMaxDynamicSharedMemorySize, SMEM_E);

    prep<<<64, 256>>>(W1, W2, W3);
    node_proj<<<nblocks, 512, SMEM_N>>>(x, N);
    edge_kernel<<<148, NT, SMEM_E>>>(ei, eattr, b1, b2, gam, bet,
                                     mean, var, b3, out, E, ntiles);
}

// round 13
// speedup vs baseline: 11.3217x; 1.0228x over previous
#include <cuda_runtime.h>
#include <cuda_fp16.h>

#define NT 384
#define EARB 144           // EA staging row stride (fp32, padded)
#define PRB  272           // P staging row stride
#define WPB  11264         // per-warp staging stride

// ---- edge-kernel smem layout ----
#define OFF_SC 0           // scale,shift,b1,b3 = 2048
#define OFF_W1 2048        // 8192
#define OFF_W2 10240       // 32768 (W2 chunk2 frags)
#define OFF_W3 43008       // 32768
#define OFF_WP 75776       // 12 warps x 11264 (EA 2304 | PR 4352 | PC 4352)
#define SMEM_E (75776 + 12 * 11264)

// ---- node-kernel smem layout ----
#define ARB  272
#define NOFF_A   0
#define NOFF_W   34816
#define NOFF_XS  100352
#define SMEM_N   165888

__device__ __align__(16) unsigned g_P[131072 * 128];
__device__ __align__(16) uint2 g_W1f[2 * 512];
__device__ __align__(16) uint2 g_W2f[24 * 512];
__device__ __align__(16) uint2 g_W3f[8 * 512];

#define CP16(dst, src)  asm volatile("cp.async.cg.shared.global [%0], [%1], 16;" :: "r"(dst), "l"(src) : "memory")
#define CP_COMMIT()     asm volatile("cp.async.commit_group;" ::: "memory")
#define CP_WAIT(n)      asm volatile("cp.async.wait_group %0;" :: "n"(n) : "memory")

__device__ __forceinline__ unsigned smem_u32(const void* p) {
    unsigned a;
    asm("{ .reg .u64 t; cvta.to.shared.u64 t, %1; cvt.u32.u64 %0, t; }" : "=r"(a) : "l"(p));
    return a;
}
__device__ __forceinline__ unsigned f22h2(float lo, float hi) {
    unsigned r;
    asm("cvt.rn.f16x2.f32 %0, %1, %2;" : "=r"(r) : "f"(hi), "f"(lo));
    return r;
}
__device__ __forceinline__ float2 h2f2(unsigned u) {
    __half2 h; *(unsigned*)&h = u;
    return __half22float2(h);
}
__device__ __forceinline__ void mma16(float* c, unsigned a0, unsigned a1, unsigned a2,
                                      unsigned a3, unsigned b0, unsigned b1) {
    asm volatile("mma.sync.aligned.m16n8k16.row.col.f32.f16.f16.f32 "
        "{%0,%1,%2,%3}, {%4,%5,%6,%7}, {%8,%9}, {%0,%1,%2,%3};"
        : "+f"(c[0]), "+f"(c[1]), "+f"(c[2]), "+f"(c[3])
        : "r"(a0), "r"(a1), "r"(a2), "r"(a3), "r"(b0), "r"(b1));
}
__device__ __forceinline__ float tanh_mufu(float v) {
    float r;
    asm("tanh.approx.f32 %0, %1;" : "=f"(r) : "f"(v));
    return r;
}
__device__ __forceinline__ void st_cs_v2(float* p, float a, float b) {
    asm volatile("st.global.cs.v2.f32 [%0], {%1,%2};" :: "l"(p), "f"(a), "f"(b) : "memory");
}

// ---- prep: weights -> fragment-major fp16 ----
__global__ void prep(const float* __restrict__ W1, const float* __restrict__ W2,
                     const float* __restrict__ W3) {
    int t = blockIdx.x * blockDim.x + threadIdx.x;
    int s = gridDim.x * blockDim.x;
    for (int i = t; i < 2 * 512; i += s) {
        int lane = i & 31, nt = (i >> 5) & 3, cq = (i >> 7) & 3, ks = i >> 9;
        int n = cq * 32 + nt * 8 + (lane >> 2), k0 = ks * 16 + (lane & 3) * 2;
        g_W1f[i] = make_uint2(f22h2(W1[k0 * 128 + n], W1[(k0 + 1) * 128 + n]),
                              f22h2(W1[(k0 + 8) * 128 + n], W1[(k0 + 9) * 128 + n]));
    }
    for (int i = t; i < 24 * 512; i += s) {
        int lane = i & 31, nt = (i >> 5) & 3, cq = (i >> 7) & 3, ks = i >> 9;
        int n = cq * 32 + nt * 8 + (lane >> 2), k0 = ks * 16 + (lane & 3) * 2;
        g_W2f[i] = make_uint2(f22h2(W2[k0 * 128 + n], W2[(k0 + 1) * 128 + n]),
                              f22h2(W2[(k0 + 8) * 128 + n], W2[(k0 + 9) * 128 + n]));
    }
    for (int i = t; i < 8 * 512; i += s) {
        int lane = i & 31, nt = (i >> 5) & 3, cq = (i >> 7) & 3, ks = i >> 9;
        int n = cq * 32 + nt * 8 + (lane >> 2), k0 = ks * 16 + (lane & 3) * 2;
        g_W3f[i] = make_uint2(f22h2(W3[k0 * 128 + n], W3[(k0 + 1) * 128 + n]),
                              f22h2(W3[(k0 + 8) * 128 + n], W3[(k0 + 9) * 128 + n]));
    }
}

// ---- node projections: P[n] = x[n] @ [W2c0 | W2c1] ----
__global__ void __launch_bounds__(512, 1)
node_proj(const float* __restrict__ x, int N) {
    extern __shared__ char smem[];
    const unsigned sb = smem_u32(smem);
    const int tid = threadIdx.x;
    const int w = tid >> 5, lane = tid & 31;
    const int gid = lane >> 2, tig = lane & 3;
    const int rb = (w >> 2) * 32, cq = w & 3, cbase = cq * 32;
    const int r4 = tid >> 2, q4 = tid & 3;

    #pragma unroll
    for (int i = 0; i < 8; i++)
        CP16(sb + NOFF_W + (i * 512 + tid) * 16, (const char*)g_W2f + (i * 512 + tid) * 16);
    {
        int node = min(blockIdx.x * 128 + r4, N - 1);
        const float* s = x + (long long)node * 128 + q4 * 32;
        unsigned d = sb + NOFF_XS + (r4 * 128 + q4 * 32) * 4;
        #pragma unroll
        for (int i = 0; i < 8; i++) CP16(d + i * 16, s + i * 4);
    }
    CP_COMMIT(); CP_WAIT(0);
    __syncthreads();

    {
        const float* s = (const float*)(smem + NOFF_XS) + r4 * 128 + q4 * 32;
        unsigned* d = (unsigned*)(smem + NOFF_A + r4 * ARB) + q4 * 16;
        #pragma unroll
        for (int i = 0; i < 16; i++) d[i] = f22h2(s[2 * i], s[2 * i + 1]);
    }
    __syncthreads();

    const char* Ath = smem + NOFF_A + (rb + gid) * ARB + tig * 4;
    const uint2* Wt = (const uint2*)(smem + NOFF_W) + cq * 128 + lane;

    float acc[2][4][4];
    #pragma unroll
    for (int ch = 0; ch < 2; ch++) {
        #pragma unroll
        for (int m = 0; m < 2; m++)
            #pragma unroll
            for (int n = 0; n < 4; n++)
                { acc[m][n][0]=0.f; acc[m][n][1]=0.f; acc[m][n][2]=0.f; acc[m][n][3]=0.f; }
        #pragma unroll
        for (int ks = 0; ks < 8; ks++) {
            unsigned a[2][4];
            #pragma unroll
            for (int mt = 0; mt < 2; mt++) {
                const char* Am = Ath + ks * 32 + mt * 16 * ARB;
                a[mt][0] = *(const unsigned*)(Am);
                a[mt][1] = *(const unsigned*)(Am + 8 * ARB);
                a[mt][2] = *(const unsigned*)(Am + 16);
                a[mt][3] = *(const unsigned*)(Am + 8 * ARB + 16);
            }
            const uint2* Bk = Wt + (ch * 8 + ks) * 512;
            #pragma unroll
            for (int nt = 0; nt < 4; nt++) {
                uint2 b = Bk[nt * 32];
                mma16(acc[0][nt], a[0][0], a[0][1], a[0][2], a[0][3], b.x, b.y);
                mma16(acc[1][nt], a[1][0], a[1][1], a[1][2], a[1][3], b.x, b.y);
            }
        }
        #pragma unroll
        for (int mt = 0; mt < 2; mt++) {
            int node0 = blockIdx.x * 128 + rb + mt * 16 + gid;
            int pcol = ch * 64 + (cbase >> 1) + tig;
            #pragma unroll
            for (int nt = 0; nt < 4; nt++) {
                if (node0 < N)
                    g_P[(long long)node0 * 128 + pcol + nt * 4] =
                        f22h2(acc[mt][nt][0], acc[mt][nt][1]);
                if (node0 + 8 < N)
                    g_P[(long long)(node0 + 8) * 128 + pcol + nt * 4] =
                        f22h2(acc[mt][nt][2], acc[mt][nt][3]);
            }
        }
    }
}

// ---- edge kernel: barrier-free per-warp streams, 16 edges x 128 cols per warp ----
__global__ void __launch_bounds__(NT, 1)
edge_kernel(const int* __restrict__ ei, const float* __restrict__ ea,
            const float* __restrict__ b1, const float* __restrict__ b2,
            const float* __restrict__ gamma, const float* __restrict__ beta,
            const float* __restrict__ mean, const float* __restrict__ var,
            const float* __restrict__ b3,
            float* __restrict__ out, int E, int nchunks)
{
    extern __shared__ char smem[];
    const unsigned sb = smem_u32(smem);
    float* sScale = (float*)(smem + OFF_SC);
    float* sShift = (float*)(smem + OFF_SC + 512);
    float* sB1    = (float*)(smem + OFF_SC + 1024);
    float* sB3    = (float*)(smem + OFF_SC + 1536);

    const int tid = threadIdx.x;
    const int w = tid >> 5, lane = tid & 31;
    const int gid = lane >> 2, tig = lane & 3;
    const int l16 = lane & 15, lh = lane >> 4;

    if (tid < 128) {
        float sc = gamma[tid] * rsqrtf(var[tid] + 1e-5f);
        sScale[tid] = sc;
        sShift[tid] = (b2[tid] - mean[tid]) * sc + beta[tid];
        sB1[tid] = b1[tid];
        sB3[tid] = b3[tid];
    }
    for (int i = tid; i < 512; i += NT)
        CP16(sb + OFF_W1 + i * 16, (const char*)g_W1f + i * 16);
    for (int i = tid; i < 2048; i += NT)
        CP16(sb + OFF_W2 + i * 16, (const char*)(g_W2f + 16 * 512) + i * 16);
    for (int i = tid; i < 2048; i += NT)
        CP16(sb + OFF_W3 + i * 16, (const char*)g_W3f + i * 16);
    CP_COMMIT(); CP_WAIT(0);
    __syncthreads();

    const bool is64 = ((ei[1] | ei[3] | ei[5] | ei[7]) == 0);
    const long long* ei64 = (const long long*)ei;

    // per-warp staging
    const unsigned wp = sb + OFF_WP + w * WPB;
    const unsigned sEA = wp;             // 16 x EARB fp32
    const unsigned sPR = wp + 2304;      // 16 x PRB
    const unsigned sPC = wp + 6656;      // 16 x PRB
    const uint2* W1t = (const uint2*)(smem + OFF_W1) + lane;
    const uint2* W2t = (const uint2*)(smem + OFF_W2) + lane;
    const uint2* W3t = (const uint2*)(smem + OFF_W3) + lane;

    #define LDIDX(dst, eb) { int _e = min((eb) + l16, E - 1); \
        long long _o = (lane < 16) ? (long long)_e : (long long)E + _e; \
        (dst) = is64 ? (int)ei64[_o] : ei[_o]; }
    #define ISSUE_EA(eb) { int _ge = min((eb) + l16, E - 1); \
        const float* _s = ea + (long long)_ge * 32 + lh * 16; \
        unsigned _d = sEA + l16 * EARB + lh * 64; \
        CP16(_d, _s); CP16(_d + 16, _s + 4); \
        CP16(_d + 32, _s + 8); CP16(_d + 48, _s + 12); CP_COMMIT(); }

    const int stride = gridDim.x * 12;
    const int c0 = blockIdx.x * 12 + w;

    int idxv;
    LDIDX(idxv, c0 * 16);
    ISSUE_EA(c0 * 16);                       // group: EA(cur)

    float acc[16][4];
    unsigned ef[32];

    for (int c = c0; c < nchunks; c += stride) {
        const int ebase = c * 16;

        // issue P gather for cur (uses idxv via shfl)
        {
            int nR = __shfl_sync(0xffffffffu, idxv, l16);
            int nC = __shfl_sync(0xffffffffu, idxv, 16 + l16);
            const char* srcR = (const char*)g_P + (long long)nR * 512 + lh * 128;
            const char* srcC = (const char*)g_P + (long long)nC * 512 + 256 + lh * 128;
            unsigned dR = sPR + l16 * PRB + lh * 128;
            unsigned dC = sPC + l16 * PRB + lh * 128;
            #pragma unroll
            for (int i = 0; i < 8; i++) CP16(dR + i * 16, srcR + i * 16);
            #pragma unroll
            for (int i = 0; i < 8; i++) CP16(dC + i * 16, srcC + i * 16);
            CP_COMMIT();                     // group: P(cur)
        }
        CP_WAIT(1);                          // EA(cur) done (P outstanding)
        __syncwarp();

        // MMA1: e = EA @ W1 (K=32), frags cvt'd from fp32 staging
        #pragma unroll
        for (int j = 0; j < 16; j++) { acc[j][0]=0.f; acc[j][1]=0.f; acc[j][2]=0.f; acc[j][3]=0.f; }
        #pragma unroll
        for (int ks = 0; ks < 2; ks++) {
            const char* Ak = (const char*)smem + (sEA - sb) + ks * 64 + tig * 8;
            float2 v0 = *(const float2*)(Ak + gid * EARB);
            float2 v1 = *(const float2*)(Ak + (gid + 8) * EARB);
            float2 v2 = *(const float2*)(Ak + gid * EARB + 32);
            float2 v3 = *(const float2*)(Ak + (gid + 8) * EARB + 32);
            unsigned a0 = f22h2(v0.x, v0.y), a1 = f22h2(v1.x, v1.y);
            unsigned a2 = f22h2(v2.x, v2.y), a3 = f22h2(v3.x, v3.y);
            #pragma unroll
            for (int blk = 0; blk < 16; blk++) {
                uint2 b = W1t[ks * 512 + (blk >> 2) * 128 + (blk & 3) * 32];
                mma16(acc[blk], a0, a1, a2, a3, b.x, b.y);
            }
        }

        // epi1: tanh in regs -> e frags (D-frag == next A-frag identity)
        #pragma unroll
        for (int j = 0; j < 16; j++) {
            float2 bb = *(const float2*)(sB1 + j * 8 + 2 * tig);
            ef[2*j]   = f22h2(tanh_mufu(acc[j][0] + bb.x), tanh_mufu(acc[j][1] + bb.y));
            ef[2*j+1] = f22h2(tanh_mufu(acc[j][2] + bb.x), tanh_mufu(acc[j][3] + bb.y));
        }

        // prefetch next chunk: EA + indices (EA buffer now free)
        int cn = c + stride;
        int nb = (cn < nchunks ? cn : c) * 16;
        ISSUE_EA(nb);                        // group: EA(next)
        LDIDX(idxv, nb);

        // MMA2: h = e @ W2c2
        #pragma unroll
        for (int j = 0; j < 16; j++) { acc[j][0]=0.f; acc[j][1]=0.f; acc[j][2]=0.f; acc[j][3]=0.f; }
        #pragma unroll
        for (int ks = 0; ks < 8; ks++) {
            #pragma unroll
            for (int blk = 0; blk < 16; blk++) {
                uint2 b = W2t[ks * 512 + (blk >> 2) * 128 + (blk & 3) * 32];
                mma16(acc[blk], ef[4*ks], ef[4*ks+1], ef[4*ks+2], ef[4*ks+3], b.x, b.y);
            }
        }
        CP_WAIT(1);                          // P(cur) done (EA(next) outstanding)
        __syncwarp();

        // epi2: h = relu((acc + Prow + Pcol)*scale + shift) in regs -> h frags
        #pragma unroll
        for (int j = 0; j < 16; j++) {
            int cc = j * 8 + 2 * tig;
            float2 sc = *(const float2*)(sScale + cc);
            float2 sh = *(const float2*)(sShift + cc);
            int po = j * 16 + tig * 4;
            float2 r0 = h2f2(*(const unsigned*)(smem + (sPR - sb) + gid * PRB + po));
            float2 q0 = h2f2(*(const unsigned*)(smem + (sPC - sb) + gid * PRB + po));
            float2 r1 = h2f2(*(const unsigned*)(smem + (sPR - sb) + (gid + 8) * PRB + po));
            float2 q1 = h2f2(*(const unsigned*)(smem + (sPC - sb) + (gid + 8) * PRB + po));
            ef[2*j] = f22h2(
                fmaxf(fmaf(acc[j][0] + r0.x + q0.x, sc.x, sh.x), 0.f),
                fmaxf(fmaf(acc[j][1] + r0.y + q0.y, sc.y, sh.y), 0.f));
            ef[2*j+1] = f22h2(
                fmaxf(fmaf(acc[j][2] + r1.x + q1.x, sc.x, sh.x), 0.f),
                fmaxf(fmaf(acc[j][3] + r1.y + q1.y, sc.y, sh.y), 0.f));
        }

        // MMA3: y = h @ W3
        #pragma unroll
        for (int j = 0; j < 16; j++) { acc[j][0]=0.f; acc[j][1]=0.f; acc[j][2]=0.f; acc[j][3]=0.f; }
        #pragma unroll
        for (int ks = 0; ks < 8; ks++) {
            #pragma unroll
            for (int blk = 0; blk < 16; blk++) {
                uint2 b = W3t[ks * 512 + (blk >> 2) * 128 + (blk & 3) * 32];
                mma16(acc[blk], ef[4*ks], ef[4*ks+1], ef[4*ks+2], ef[4*ks+3], b.x, b.y);
            }
        }

        // epi3: relu(y + b3) -> gmem
        {
            int e0 = ebase + gid, e1 = ebase + gid + 8;
            float* po0 = out + (long long)e0 * 128;
            float* po1 = out + (long long)e1 * 128;
            #pragma unroll
            for (int j = 0; j < 16; j++) {
                int cc = j * 8 + 2 * tig;
                float2 bb = *(const float2*)(sB3 + cc);
                if (e0 < E) st_cs_v2(po0 + cc, fmaxf(acc[j][0] + bb.x, 0.f),
                                               fmaxf(acc[j][1] + bb.y, 0.f));
                if (e1 < E) st_cs_v2(po1 + cc, fmaxf(acc[j][2] + bb.x, 0.f),
                                               fmaxf(acc[j][3] + bb.y, 0.f));
            }
        }
    }
    CP_WAIT(0);
}

extern "C" void kernel_launch(void* const* d_in, const int* in_sizes, int n_in,
                              void* d_out, int out_size) {
    const float* x     = (const float*)d_in[0];
    const int*   ei    = (const int*)  d_in[1];
    const float* eattr = (const float*)d_in[2];
    const float* W1    = (const float*)d_in[3];
    const float* b1    = (const float*)d_in[4];
    const float* W2    = (const float*)d_in[5];
    const float* b2    = (const float*)d_in[6];
    const float* gam   = (const float*)d_in[7];
    const float* bet   = (const float*)d_in[8];
    const float* mean  = (const float*)d_in[9];
    const float* var   = (const float*)d_in[10];
    const float* W3    = (const float*)d_in[11];
    const float* b3    = (const float*)d_in[12];
    float* out = (float*)d_out;

    int N = in_sizes[0] / 128;
    int E = in_sizes[2] / 32;
    int nchunks = (E + 15) / 16;
    int nblocks = (N + 127) / 128;

    cudaFuncSetAttribute(node_proj, cudaFuncAttributeMaxDynamicSharedMemorySize, SMEM_N);
    cudaFuncSetAttribute(edge_kernel, cudaFuncAttributeMaxDynamicSharedMemorySize, SMEM_E);

    prep<<<64, 256>>>(W1, W2, W3);
    node_proj<<<nblocks, 512, SMEM_N>>>(x, N);
    edge_kernel<<<148, NT, SMEM_E>>>(ei, eattr, b1, b2, gam, bet,
                                     mean, var, b3, out, E, nchunks);
}